// round 1
// baseline (speedup 1.0000x reference)
#include <cuda_runtime.h>
#include <math.h>

#define NB 4
#define NC 256
#define NK 32
#define NPOS 4096

// Scratch (device globals: no allocation allowed in kernel_launch)
__device__ float g_Q[(size_t)NB * NPOS * NK];   // [B][N][32]
__device__ float g_K[(size_t)NB * NPOS * NK];   // [B][N][32]
__device__ float g_V[(size_t)NB * NPOS * NC];   // [B][N][256]

// ---------------------------------------------------------------------------
// Projection: out[k][n] = sum_c Wcat[k][c] * x[b][c][n],  Wcat = [w1;w2;w3] (320x256)
// rows 0..31 -> Q, 32..63 -> K, 64..319 -> V
// Tiles: 64 k-rows x 128 n-cols, K-chunk 32. 256 threads (16x16), 4x8 micro-tile.
// ---------------------------------------------------------------------------
__global__ __launch_bounds__(256) void proj_kernel(
    const float* __restrict__ x, const float* __restrict__ w1,
    const float* __restrict__ w2, const float* __restrict__ w3)
{
    const int n0 = blockIdx.x * 128;
    const int k0 = blockIdx.y * 64;
    const int b  = blockIdx.z;

    __shared__ float As[64 * 33];      // W tile [64][32], stride 33
    __shared__ float Bs[32 * 132];     // x tile [32][128], stride 132

    const int t  = threadIdx.x;
    const int ty = t >> 4;             // 0..15
    const int tx = t & 15;             // 0..15

    float acc[4][8];
#pragma unroll
    for (int r = 0; r < 4; r++)
#pragma unroll
        for (int c = 0; c < 8; c++) acc[r][c] = 0.f;

    const float* xb = x + (size_t)b * NC * NPOS;

    for (int c0 = 0; c0 < NC; c0 += 32) {
        // Load W tile: 64x32 = 2048 floats, 8 per thread
#pragma unroll
        for (int i = 0; i < 8; i++) {
            int idx = t + i * 256;
            int kk = idx >> 5;
            int cc = idx & 31;
            int kg = k0 + kk;
            const float* wp; int row;
            if (kg < 32)       { wp = w1; row = kg; }
            else if (kg < 64)  { wp = w2; row = kg - 32; }
            else               { wp = w3; row = kg - 64; }
            As[kk * 33 + cc] = wp[row * NC + c0 + cc];
        }
        // Load x tile: 32x128 floats as float4, 4 per thread
#pragma unroll
        for (int i = 0; i < 4; i++) {
            int idx = t + i * 256;          // 0..1023 float4 index
            int cc = idx >> 5;              // 0..31
            int n4 = idx & 31;              // 0..31
            float4 v = *(const float4*)(xb + (size_t)(c0 + cc) * NPOS + n0 + n4 * 4);
            *(float4*)(Bs + cc * 132 + n4 * 4) = v;
        }
        __syncthreads();

#pragma unroll
        for (int cc = 0; cc < 32; cc++) {
            float a[4], bb[8];
#pragma unroll
            for (int r = 0; r < 4; r++) a[r] = As[(ty * 4 + r) * 33 + cc];
#pragma unroll
            for (int c = 0; c < 8; c++) bb[c] = Bs[cc * 132 + tx * 8 + c];
#pragma unroll
            for (int r = 0; r < 4; r++)
#pragma unroll
                for (int c = 0; c < 8; c++) acc[r][c] = fmaf(a[r], bb[c], acc[r][c]);
        }
        __syncthreads();
    }

    // Store to Q/K/V
#pragma unroll
    for (int r = 0; r < 4; r++) {
        int kg = k0 + ty * 4 + r;
#pragma unroll
        for (int i = 0; i < 8; i++) {
            int n = n0 + tx * 8 + i;
            float v = acc[r][i];
            if (kg < 32)
                g_Q[((size_t)b * NPOS + n) * NK + kg] = v;
            else if (kg < 64)
                g_K[((size_t)b * NPOS + n) * NK + (kg - 32)] = v;
            else
                g_V[((size_t)b * NPOS + n) * NC + (kg - 64)] = v;
        }
    }
}

// ---------------------------------------------------------------------------
// Fused flash attention + residual + transposed store.
// Per CTA: batch b, 64 query rows. 256 threads = 8 warps.
// Warp ty owns query rows [ty*8, ty*8+8).
// Phase A: S = Q K^T over a 64-key tile; cols split 2/lane; warp-shuffle
//          row max/sum; online softmax; P -> smem.
// Phase B: O += P @ V with 8x8 register micro-tile (rows ty*8.., cols tx*8..).
// ---------------------------------------------------------------------------
#define QS_STRIDE 36
#define PS_STRIDE 68
#define SMEM_FLOATS (64*QS_STRIDE + 64*QS_STRIDE + 64*PS_STRIDE + 64*NC + 192)
#define SMEM_BYTES (SMEM_FLOATS * 4)

__global__ __launch_bounds__(256) void attn_kernel(
    const float* __restrict__ x, float* __restrict__ out)
{
    const int b  = blockIdx.y;
    const int q0 = blockIdx.x * 64;
    const int t  = threadIdx.x;
    const int ty = t >> 5;       // warp 0..7
    const int tx = t & 31;       // lane

    extern __shared__ float sm[];
    float* Qs  = sm;                          // [64][36]
    float* Ks  = Qs + 64 * QS_STRIDE;         // [64][36]
    float* Ps  = Ks + 64 * QS_STRIDE;         // [64][68]
    float* Vs  = Ps + 64 * PS_STRIDE;         // [64][256]
    float* ms  = Vs + 64 * NC;                // [64]
    float* ls  = ms + 64;                     // [64]
    float* as_ = ls + 64;                     // [64]

    // Load Q tile
    for (int i = t; i < 64 * NK; i += 256) {
        int row = i >> 5, c = i & 31;
        Qs[row * QS_STRIDE + c] = g_Q[((size_t)b * NPOS + q0 + row) * NK + c];
    }
    if (t < 64) { ms[t] = -1e30f; ls[t] = 0.f; }

    float acc[8][8];
#pragma unroll
    for (int r = 0; r < 8; r++)
#pragma unroll
        for (int c = 0; c < 8; c++) acc[r][c] = 0.f;

    __syncthreads();

    const float4* Q4 = (const float4*)Qs;
    const float4* K4 = (const float4*)Ks;
    const float4* V4 = (const float4*)Vs;

    for (int j0 = 0; j0 < NPOS; j0 += 64) {
        // Load K tile [64][32]
        for (int i = t; i < 64 * NK; i += 256) {
            int row = i >> 5, c = i & 31;
            Ks[row * QS_STRIDE + c] = g_K[((size_t)b * NPOS + j0 + row) * NK + c];
        }
        // Load V tile [64][256] (float4, contiguous)
        {
            const float4* vg = (const float4*)(g_V + ((size_t)b * NPOS + j0) * NC);
            float4* vd = (float4*)Vs;
            for (int i = t; i < 64 * NC / 4; i += 256) vd[i] = vg[i];
        }
        __syncthreads();

        // ---- Phase A: scores + online softmax ----
        float s[8][2];
#pragma unroll
        for (int r = 0; r < 8; r++) { s[r][0] = 0.f; s[r][1] = 0.f; }

        const int kr0 = (tx * 2) * (QS_STRIDE / 4);      // float4 row offsets
        const int kr1 = (tx * 2 + 1) * (QS_STRIDE / 4);
#pragma unroll
        for (int c4 = 0; c4 < 8; c4++) {
            float4 kv0 = K4[kr0 + c4];
            float4 kv1 = K4[kr1 + c4];
#pragma unroll
            for (int rr = 0; rr < 8; rr++) {
                float4 qv = Q4[(ty * 8 + rr) * (QS_STRIDE / 4) + c4];
                s[rr][0] += qv.x * kv0.x + qv.y * kv0.y + qv.z * kv0.z + qv.w * kv0.w;
                s[rr][1] += qv.x * kv1.x + qv.y * kv1.y + qv.z * kv1.z + qv.w * kv1.w;
            }
        }

#pragma unroll
        for (int rr = 0; rr < 8; rr++) {
            int row = ty * 8 + rr;
            float mloc = fmaxf(s[rr][0], s[rr][1]);
#pragma unroll
            for (int off = 16; off >= 1; off >>= 1)
                mloc = fmaxf(mloc, __shfl_xor_sync(0xffffffffu, mloc, off));
            float mold = ms[row];
            float mnew = fmaxf(mold, mloc);
            float p0 = __expf(s[rr][0] - mnew);
            float p1 = __expf(s[rr][1] - mnew);
            float psum = p0 + p1;
#pragma unroll
            for (int off = 16; off >= 1; off >>= 1)
                psum += __shfl_xor_sync(0xffffffffu, psum, off);
            if (tx == 0) {
                float alpha = __expf(mold - mnew);
                ms[row]  = mnew;
                as_[row] = alpha;
                ls[row]  = ls[row] * alpha + psum;
            }
            Ps[row * PS_STRIDE + tx * 2]     = p0;
            Ps[row * PS_STRIDE + tx * 2 + 1] = p1;
        }
        __syncthreads();

        // ---- Phase B: O = O*alpha + P @ V ----
#pragma unroll
        for (int rr = 0; rr < 8; rr++) {
            float alpha = as_[ty * 8 + rr];
#pragma unroll
            for (int cc = 0; cc < 8; cc++) acc[rr][cc] *= alpha;
        }

#pragma unroll 2
        for (int j = 0; j < 64; j++) {
            float4 v0 = V4[j * (NC / 4) + tx * 2];
            float4 v1 = V4[j * (NC / 4) + tx * 2 + 1];
#pragma unroll
            for (int rr = 0; rr < 8; rr++) {
                float p = Ps[(ty * 8 + rr) * PS_STRIDE + j];
                acc[rr][0] = fmaf(p, v0.x, acc[rr][0]);
                acc[rr][1] = fmaf(p, v0.y, acc[rr][1]);
                acc[rr][2] = fmaf(p, v0.z, acc[rr][2]);
                acc[rr][3] = fmaf(p, v0.w, acc[rr][3]);
                acc[rr][4] = fmaf(p, v1.x, acc[rr][4]);
                acc[rr][5] = fmaf(p, v1.y, acc[rr][5]);
                acc[rr][6] = fmaf(p, v1.z, acc[rr][6]);
                acc[rr][7] = fmaf(p, v1.w, acc[rr][7]);
            }
        }
        __syncthreads();
    }

    // ---- Epilogue: divide by l, add residual, store transposed ----
    float invl[8];
#pragma unroll
    for (int rr = 0; rr < 8; rr++) invl[rr] = 1.f / ls[ty * 8 + rr];

#pragma unroll
    for (int cc = 0; cc < 8; cc++) {
        int c = tx * 8 + cc;
        size_t base = ((size_t)b * NC + c) * NPOS + q0 + ty * 8;  // 8 consecutive n
        float4 x0 = *(const float4*)(x + base);
        float4 x1 = *(const float4*)(x + base + 4);
        float4 o0 = make_float4(acc[0][cc] * invl[0] + x0.x,
                                acc[1][cc] * invl[1] + x0.y,
                                acc[2][cc] * invl[2] + x0.z,
                                acc[3][cc] * invl[3] + x0.w);
        float4 o1 = make_float4(acc[4][cc] * invl[4] + x1.x,
                                acc[5][cc] * invl[5] + x1.y,
                                acc[6][cc] * invl[6] + x1.z,
                                acc[7][cc] * invl[7] + x1.w);
        *(float4*)(out + base)     = o0;
        *(float4*)(out + base + 4) = o1;
    }
}

// ---------------------------------------------------------------------------
extern "C" void kernel_launch(void* const* d_in, const int* in_sizes, int n_in,
                              void* d_out, int out_size)
{
    const float* x  = (const float*)d_in[0];
    const float* w1 = (const float*)d_in[1];
    const float* w2 = (const float*)d_in[2];
    const float* w3 = (const float*)d_in[3];
    float* out = (float*)d_out;

    cudaFuncSetAttribute(attn_kernel, cudaFuncAttributeMaxDynamicSharedMemorySize,
                         SMEM_BYTES);

    dim3 gproj(NPOS / 128, 320 / 64, NB);   // (32, 5, 4)
    proj_kernel<<<gproj, 256>>>(x, w1, w2, w3);

    dim3 gattn(NPOS / 64, NB);              // (64, 4)
    attn_kernel<<<gattn, 256, SMEM_BYTES>>>(x, out);
}

// round 4
// speedup vs baseline: 3.8026x; 3.8026x over previous
#include <cuda_runtime.h>
#include <cstdint>

#define NB 4
#define NC 256
#define NK 32
#define NPOS 4096
#define QM 128
#define TK 32
#define NT (NPOS / TK)    // 128
#define THREADS 512

// ---------------- scratch (device globals; no allocs allowed) ---------------
__device__ __align__(128) float g_Q[(size_t)NB * NPOS * NK];   // [b][n][32]
__device__ __align__(128) float g_K[(size_t)NB * NPOS * NK];   // [b][n][32]
__device__ __align__(128) float g_V[(size_t)NB * NPOS * NC];   // [b][n][256]

// ---------------- helpers ---------------------------------------------------
__device__ __forceinline__ uint32_t s2u(const void* p) {
    uint32_t a;
    asm("{ .reg .u64 t; cvta.to.shared.u64 t, %1; cvt.u32.u64 %0, t; }"
        : "=r"(a) : "l"(p));
    return a;
}
__device__ __forceinline__ void cp16(uint32_t s, const void* g) {
    asm volatile("cp.async.cg.shared.global [%0], [%1], 16;" :: "r"(s), "l"(g));
}
#define CP_COMMIT() asm volatile("cp.async.commit_group;" ::: "memory")
#define CP_WAIT(n)  asm volatile("cp.async.wait_group %0;" :: "n"(n) : "memory")

__device__ __forceinline__ float tf32r(float v) {
    uint32_t u; asm("cvt.rna.tf32.f32 %0, %1;" : "=r"(u) : "f"(v));
    return __uint_as_float(u);
}
__device__ __forceinline__ uint32_t tf32u(float v) {
    uint32_t u; asm("cvt.rna.tf32.f32 %0, %1;" : "=r"(u) : "f"(v));
    return u;
}

// m16n8k8 tf32 mma: D += A * B  (A row-major 16x8, B col-major 8x8)
__device__ __forceinline__ void mma8(float* c, const uint32_t* a,
                                     uint32_t b0, uint32_t b1) {
    asm volatile(
        "mma.sync.aligned.m16n8k8.row.col.f32.tf32.tf32.f32 "
        "{%0,%1,%2,%3}, {%4,%5,%6,%7}, {%8,%9}, {%0,%1,%2,%3};"
        : "+f"(c[0]), "+f"(c[1]), "+f"(c[2]), "+f"(c[3])
        : "r"(a[0]), "r"(a[1]), "r"(a[2]), "r"(a[3]), "r"(b0), "r"(b1));
}

// SMEM float offsets
#define QSTR 36
#define VSTR 264
#define OFF_Q 0                               // [128][36]
#define OFF_K (OFF_Q + QM * QSTR)             // 2 x [32][36]
#define OFF_V (OFF_K + 2 * TK * QSTR)         // 2 x [32][264]
#define OFF_P (OFF_V + 2 * TK * VSTR)         // [128][36]
#define OFF_L (OFF_P + QM * QSTR)             // [128]
#define SMEM_FLOATS (OFF_L + QM)
#define SMEM_BYTES (SMEM_FLOATS * 4)          // ~111.5 KB

// ---------------------------------------------------------------------------
// Projection: Wcat[320,256] @ x[b][256][4096]; rows 0..31->Q, 32..63->K, rest->V.
// All outputs tf32-rounded. V stored [b][n][d].
// ---------------------------------------------------------------------------
__global__ __launch_bounds__(256) void proj_kernel(
    const float* __restrict__ x, const float* __restrict__ w1,
    const float* __restrict__ w2, const float* __restrict__ w3)
{
    const int n0 = blockIdx.x * 128;
    const int k0 = blockIdx.y * 64;
    const int b  = blockIdx.z;

    __shared__ float As[64 * 33];
    __shared__ float Bs[32 * 132];

    const int t  = threadIdx.x;
    const int ty = t >> 4;
    const int tx = t & 15;

    float acc[4][8];
#pragma unroll
    for (int r = 0; r < 4; r++)
#pragma unroll
        for (int c = 0; c < 8; c++) acc[r][c] = 0.f;

    const float* xb = x + (size_t)b * NC * NPOS;

    for (int c0 = 0; c0 < NC; c0 += 32) {
#pragma unroll
        for (int i = 0; i < 8; i++) {
            int idx = t + i * 256;
            int kk = idx >> 5, cc = idx & 31;
            int kg = k0 + kk;
            const float* wp; int row;
            if (kg < 32)      { wp = w1; row = kg; }
            else if (kg < 64) { wp = w2; row = kg - 32; }
            else              { wp = w3; row = kg - 64; }
            As[kk * 33 + cc] = wp[row * NC + c0 + cc];
        }
#pragma unroll
        for (int i = 0; i < 4; i++) {
            int idx = t + i * 256;
            int cc = idx >> 5, n4 = idx & 31;
            float4 v = *(const float4*)(xb + (size_t)(c0 + cc) * NPOS + n0 + n4 * 4);
            *(float4*)(Bs + cc * 132 + n4 * 4) = v;
        }
        __syncthreads();
#pragma unroll
        for (int cc = 0; cc < 32; cc++) {
            float a[4], bb[8];
#pragma unroll
            for (int r = 0; r < 4; r++) a[r] = As[(ty * 4 + r) * 33 + cc];
#pragma unroll
            for (int c = 0; c < 8; c++) bb[c] = Bs[cc * 132 + tx * 8 + c];
#pragma unroll
            for (int r = 0; r < 4; r++)
#pragma unroll
                for (int c = 0; c < 8; c++) acc[r][c] = fmaf(a[r], bb[c], acc[r][c]);
        }
        __syncthreads();
    }

#pragma unroll
    for (int r = 0; r < 4; r++) {
        int kg = k0 + ty * 4 + r;
#pragma unroll
        for (int i = 0; i < 8; i++) {
            int n = n0 + tx * 8 + i;
            float v = tf32r(acc[r][i]);
            if (kg < 32)
                g_Q[((size_t)b * NPOS + n) * NK + kg] = v;
            else if (kg < 64)
                g_K[((size_t)b * NPOS + n) * NK + (kg - 32)] = v;
            else
                g_V[((size_t)b * NPOS + n) * NC + (kg - 64)] = v;
        }
    }
}

// ---------------------------------------------------------------------------
// Flash attention, mma.sync tf32. CTA = 128 q-rows x 256 d. 16 warps:
// mg = wid&7 (16 q-rows each), dh = wid>>3 (128 d-cols each).
// dh==0 warps also compute S = QK^T, exp, write P.
// ---------------------------------------------------------------------------
__global__ __launch_bounds__(THREADS) void attn_kernel(
    const float* __restrict__ x, float* __restrict__ out)
{
    extern __shared__ float S[];
    const uint32_t sb = s2u(S);

    const int t   = threadIdx.x;
    const int wid = t >> 5;
    const int lid = t & 31;
    const int gid = lid >> 2;   // 0..7
    const int tig = lid & 3;    // 0..3
    const int mg  = wid & 7;
    const int dh  = wid >> 3;

    const int b  = blockIdx.y;
    const int q0 = blockIdx.x * QM;

    // ---- prologue: Q (group 0), K0+V0 (group 1) ----
    {
        const float* Qg = g_Q + ((size_t)b * NPOS + q0) * NK;
#pragma unroll
        for (int s = 0; s < 2; s++) {
            int i = t + s * THREADS;            // 0..1023
            int row = i >> 3, c4 = i & 7;
            cp16(sb + (OFF_Q + row * QSTR) * 4 + c4 * 16, Qg + row * NK + c4 * 4);
        }
        CP_COMMIT();
        const float* Kg = g_K + (size_t)b * NPOS * NK;
        if (t < 256) {
            int row = t >> 3, c4 = t & 7;
            cp16(sb + (OFF_K + row * QSTR) * 4 + c4 * 16, Kg + row * NK + c4 * 4);
        }
        const float* Vg = g_V + (size_t)b * NPOS * NC;
#pragma unroll
        for (int s = 0; s < 4; s++) {
            int i = t + s * THREADS;            // 0..2047
            int key = i >> 6, d4 = i & 63;
            cp16(sb + (OFF_V + key * VSTR) * 4 + d4 * 16, Vg + key * NC + d4 * 4);
        }
        CP_COMMIT();
    }

    float o[16][4];
#pragma unroll
    for (int n = 0; n < 16; n++)
#pragma unroll
        for (int c = 0; c < 4; c++) o[n][c] = 0.f;

    float l0 = 0.f, l1 = 0.f;
    uint32_t qa[4][4];

    for (int j = 0; j < NT; j++) {
        CP_WAIT(0);
        __syncthreads();

        if (j == 0 && dh == 0) {
            // load Q fragments once (Q ready since group 0 drained)
            const int r0 = mg * 16 + gid;
#pragma unroll
            for (int k = 0; k < 4; k++) {
                qa[k][0] = __float_as_uint(S[OFF_Q + r0 * QSTR + k * 8 + tig]);
                qa[k][1] = __float_as_uint(S[OFF_Q + (r0 + 8) * QSTR + k * 8 + tig]);
                qa[k][2] = __float_as_uint(S[OFF_Q + r0 * QSTR + k * 8 + tig + 4]);
                qa[k][3] = __float_as_uint(S[OFF_Q + (r0 + 8) * QSTR + k * 8 + tig + 4]);
            }
        }

        // prefetch tile j+1 into the other buffer (readers of that buffer
        // finished before the barrier above)
        if (j + 1 < NT) {
            const int nb_ = (j + 1) & 1;
            const float* Kg = g_K + ((size_t)b * NPOS + (size_t)(j + 1) * TK) * NK;
            if (t < 256) {
                int row = t >> 3, c4 = t & 7;
                cp16(sb + (OFF_K + nb_ * TK * QSTR + row * QSTR) * 4 + c4 * 16,
                     Kg + row * NK + c4 * 4);
            }
            const float* Vg = g_V + ((size_t)b * NPOS + (size_t)(j + 1) * TK) * NC;
#pragma unroll
            for (int s = 0; s < 4; s++) {
                int i = t + s * THREADS;
                int key = i >> 6, d4 = i & 63;
                cp16(sb + (OFF_V + nb_ * TK * VSTR + key * VSTR) * 4 + d4 * 16,
                     Vg + key * NC + d4 * 4);
            }
            CP_COMMIT();
        }

        // ---- QK^T + exp + P (dh==0 warps) ----
        if (dh == 0) {
            const float* Kb = S + OFF_K + (j & 1) * TK * QSTR;
            float s4[4][4];
#pragma unroll
            for (int n = 0; n < 4; n++)
#pragma unroll
                for (int c = 0; c < 4; c++) s4[n][c] = 0.f;

#pragma unroll
            for (int n = 0; n < 4; n++) {
                const int key = n * 8 + gid;
#pragma unroll
                for (int k = 0; k < 4; k++) {
                    uint32_t b0 = __float_as_uint(Kb[key * QSTR + k * 8 + tig]);
                    uint32_t b1 = __float_as_uint(Kb[key * QSTR + k * 8 + tig + 4]);
                    mma8(s4[n], qa[k], b0, b1);
                }
            }

            const int r0 = mg * 16 + gid;
#pragma unroll
            for (int n = 0; n < 4; n++) {
                float e0 = __expf(s4[n][0]);
                float e1 = __expf(s4[n][1]);
                float e2 = __expf(s4[n][2]);
                float e3 = __expf(s4[n][3]);
                l0 += e0 + e1;
                l1 += e2 + e3;
                float2 p01 = make_float2(__uint_as_float(tf32u(e0)),
                                         __uint_as_float(tf32u(e1)));
                float2 p23 = make_float2(__uint_as_float(tf32u(e2)),
                                         __uint_as_float(tf32u(e3)));
                *(float2*)&S[OFF_P + r0 * QSTR + n * 8 + 2 * tig] = p01;
                *(float2*)&S[OFF_P + (r0 + 8) * QSTR + n * 8 + 2 * tig] = p23;
            }
        }
        __syncthreads();

        // ---- O += P @ V (all warps; warp covers 16 rows x 128 cols) ----
        {
            const float* Vb = S + OFF_V + (j & 1) * TK * VSTR;
            const int r0 = mg * 16 + gid;
            uint32_t pa[4][4];
#pragma unroll
            for (int k = 0; k < 4; k++) {
                pa[k][0] = __float_as_uint(S[OFF_P + r0 * QSTR + k * 8 + tig]);
                pa[k][1] = __float_as_uint(S[OFF_P + (r0 + 8) * QSTR + k * 8 + tig]);
                pa[k][2] = __float_as_uint(S[OFF_P + r0 * QSTR + k * 8 + tig + 4]);
                pa[k][3] = __float_as_uint(S[OFF_P + (r0 + 8) * QSTR + k * 8 + tig + 4]);
            }
#pragma unroll
            for (int n = 0; n < 16; n++) {
                const int d0 = dh * 128 + n * 8 + gid;
#pragma unroll
                for (int k = 0; k < 4; k++) {
                    uint32_t b0 = __float_as_uint(Vb[(k * 8 + tig) * VSTR + d0]);
                    uint32_t b1 = __float_as_uint(Vb[(k * 8 + tig + 4) * VSTR + d0]);
                    mma8(o[n], pa[k], b0, b1);
                }
            }
        }
    }

    // ---- l reduction across quads, share via smem ----
    if (dh == 0) {
        l0 += __shfl_xor_sync(0xffffffffu, l0, 1);
        l0 += __shfl_xor_sync(0xffffffffu, l0, 2);
        l1 += __shfl_xor_sync(0xffffffffu, l1, 1);
        l1 += __shfl_xor_sync(0xffffffffu, l1, 2);
        if (tig == 0) {
            S[OFF_L + mg * 16 + gid]     = l0;
            S[OFF_L + mg * 16 + 8 + gid] = l1;
        }
    }
    __syncthreads();

    const int r0 = mg * 16 + gid;
    const float inv0 = 1.f / S[OFF_L + r0];
    const float inv1 = 1.f / S[OFF_L + r0 + 8];
    const int q = q0 + r0;

#pragma unroll
    for (int n = 0; n < 16; n++) {
        const int d0 = dh * 128 + n * 8 + 2 * tig;
        size_t i0 = ((size_t)(b * NC + d0)) * NPOS + q;
        out[i0]            = o[n][0] * inv0 + x[i0];
        out[i0 + NPOS]     = o[n][1] * inv0 + x[i0 + NPOS];
        out[i0 + 8]        = o[n][2] * inv1 + x[i0 + 8];
        out[i0 + NPOS + 8] = o[n][3] * inv1 + x[i0 + NPOS + 8];
    }
}

// ---------------------------------------------------------------------------
extern "C" void kernel_launch(void* const* d_in, const int* in_sizes, int n_in,
                              void* d_out, int out_size)
{
    const float* x  = (const float*)d_in[0];
    const float* w1 = (const float*)d_in[1];
    const float* w2 = (const float*)d_in[2];
    const float* w3 = (const float*)d_in[3];
    float* out = (float*)d_out;

    cudaFuncSetAttribute(attn_kernel, cudaFuncAttributeMaxDynamicSharedMemorySize,
                         SMEM_BYTES);

    dim3 gproj(NPOS / 128, 320 / 64, NB);
    proj_kernel<<<gproj, 256>>>(x, w1, w2, w3);

    dim3 gattn(NPOS / QM, NB);  // (32, 4)
    attn_kernel<<<gattn, THREADS, SMEM_BYTES>>>(x, out);
}

// round 5
// speedup vs baseline: 4.4003x; 1.1572x over previous
#include <cuda_runtime.h>
#include <cstdint>

#define NB 4
#define NC 256
#define NK 32
#define NPOS 4096
#define QM 128
#define TK 64
#define NT (NPOS / TK)    // 64
#define THREADS 512
#define LOG2E 1.4426950408889634f

// ---------------- scratch (device globals; no allocs allowed) ---------------
// Q,K: [b][c=32][n=4096]   V: [b][d=256][n=4096]
__device__ __align__(128) float g_Q[(size_t)NB * NK * NPOS];
__device__ __align__(128) float g_K[(size_t)NB * NK * NPOS];
__device__ __align__(128) float g_V[(size_t)NB * NC * NPOS];

// ---------------- helpers ---------------------------------------------------
__device__ __forceinline__ uint32_t s2u(const void* p) {
    uint32_t a;
    asm("{ .reg .u64 t; cvta.to.shared.u64 t, %1; cvt.u32.u64 %0, t; }"
        : "=r"(a) : "l"(p));
    return a;
}
__device__ __forceinline__ void cp16(uint32_t s, const void* g) {
    asm volatile("cp.async.cg.shared.global [%0], [%1], 16;" :: "r"(s), "l"(g));
}
#define CP_COMMIT() asm volatile("cp.async.commit_group;" ::: "memory")
#define CP_WAIT(n)  asm volatile("cp.async.wait_group %0;" :: "n"(n) : "memory")

__device__ __forceinline__ float tf32r(float v) {
    uint32_t u; asm("cvt.rna.tf32.f32 %0, %1;" : "=r"(u) : "f"(v));
    return __uint_as_float(u);
}
__device__ __forceinline__ uint32_t tf32u(float v) {
    uint32_t u; asm("cvt.rna.tf32.f32 %0, %1;" : "=r"(u) : "f"(v));
    return u;
}
__device__ __forceinline__ float ex2f(float x) {
    float r; asm("ex2.approx.f32 %0, %1;" : "=f"(r) : "f"(x)); return r;
}
__device__ __forceinline__ uint32_t fu(float v) { return __float_as_uint(v); }

// m16n8k8 tf32 mma: D += A * B
__device__ __forceinline__ void mma8(float* c, const uint32_t* a,
                                     uint32_t b0, uint32_t b1) {
    asm volatile(
        "mma.sync.aligned.m16n8k8.row.col.f32.tf32.tf32.f32 "
        "{%0,%1,%2,%3}, {%4,%5,%6,%7}, {%8,%9}, {%0,%1,%2,%3};"
        : "+f"(c[0]), "+f"(c[1]), "+f"(c[2]), "+f"(c[3])
        : "r"(a[0]), "r"(a[1]), "r"(a[2]), "r"(a[3]), "r"(b0), "r"(b1));
}

// ---- attn smem (float offsets) ----
// Q tile [32 c][132]         (q-major cols)
// K tile 2 x [32 c][68]      (key cols)
// V tile 2 x [256 d][68]     (key cols)
// P tile [128 q][68]         (key cols)
// L      [4 dc][128]
#define QS2 132
#define KS2 68
#define VS2 68
#define PS2 68
#define KBUF (32 * KS2)        // 2176
#define VBUF (NC * VS2)        // 17408
#define OFF_Q 0
#define OFF_K (OFF_Q + 32 * QS2)          // 4224
#define OFF_V (OFF_K + 2 * KBUF)          // 8576
#define OFF_P (OFF_V + 2 * VBUF)          // 43392
#define OFF_L (OFF_P + QM * PS2)          // 52096
#define SMEM_FLOATS (OFF_L + 4 * QM)      // 52608
#define SMEM_BYTES (SMEM_FLOATS * 4)      // 210432

// ---------------------------------------------------------------------------
// Projection: Wcat[320,256] @ x[b][256][4096].
// rows 0..31 -> Q (*log2e), 32..63 -> K, 64..319 -> V. All tf32-rounded.
// Outputs stored feature-major -> contiguous float4 stores.
// CTA: 64 k-rows x 256 n-cols, 256 threads, 8x8 micro-tile.
// ---------------------------------------------------------------------------
__global__ __launch_bounds__(256) void proj_kernel(
    const float* __restrict__ x, const float* __restrict__ w1,
    const float* __restrict__ w2, const float* __restrict__ w3)
{
    const int n0 = blockIdx.x * 256;
    const int k0 = blockIdx.y * 64;
    const int b  = blockIdx.z;

    __shared__ float As[64 * 33];     // W tile
    __shared__ float Bs[32 * 256];    // x tile

    const int t  = threadIdx.x;
    const int ty = t >> 5;            // 0..7  -> rows ty*8..+8
    const int tx = t & 31;            // 0..31 -> cols tx*4.. and 128+tx*4..

    float acc[8][8];
#pragma unroll
    for (int r = 0; r < 8; r++)
#pragma unroll
        for (int c = 0; c < 8; c++) acc[r][c] = 0.f;

    const float* xb = x + (size_t)b * NC * NPOS;

    for (int c0 = 0; c0 < NC; c0 += 32) {
#pragma unroll
        for (int i = 0; i < 8; i++) {
            int idx = t + i * 256;
            int kk = idx >> 5, cc = idx & 31;
            int kg = k0 + kk;
            const float* wp; int row;
            if (kg < 32)      { wp = w1; row = kg; }
            else if (kg < 64) { wp = w2; row = kg - 32; }
            else              { wp = w3; row = kg - 64; }
            As[kk * 33 + cc] = wp[row * NC + c0 + cc];
        }
#pragma unroll
        for (int i = 0; i < 8; i++) {
            int idx = t + i * 256;           // float4 index
            int cc = idx >> 6, n4 = idx & 63;
            float4 v = *(const float4*)(xb + (size_t)(c0 + cc) * NPOS + n0 + n4 * 4);
            *(float4*)(Bs + cc * 256 + n4 * 4) = v;
        }
        __syncthreads();
#pragma unroll
        for (int cc = 0; cc < 32; cc++) {
            float a[8];
#pragma unroll
            for (int r = 0; r < 8; r++) a[r] = As[(ty * 8 + r) * 33 + cc];
            float4 b0 = *(const float4*)(Bs + cc * 256 + tx * 4);
            float4 b1 = *(const float4*)(Bs + cc * 256 + 128 + tx * 4);
#pragma unroll
            for (int r = 0; r < 8; r++) {
                acc[r][0] = fmaf(a[r], b0.x, acc[r][0]);
                acc[r][1] = fmaf(a[r], b0.y, acc[r][1]);
                acc[r][2] = fmaf(a[r], b0.z, acc[r][2]);
                acc[r][3] = fmaf(a[r], b0.w, acc[r][3]);
                acc[r][4] = fmaf(a[r], b1.x, acc[r][4]);
                acc[r][5] = fmaf(a[r], b1.y, acc[r][5]);
                acc[r][6] = fmaf(a[r], b1.z, acc[r][6]);
                acc[r][7] = fmaf(a[r], b1.w, acc[r][7]);
            }
        }
        __syncthreads();
    }

#pragma unroll
    for (int r = 0; r < 8; r++) {
        int kg = k0 + ty * 8 + r;
        float* dst; float sc;
        if (kg < 32)      { dst = g_Q + ((size_t)b * NK + kg) * NPOS;        sc = LOG2E; }
        else if (kg < 64) { dst = g_K + ((size_t)b * NK + (kg - 32)) * NPOS; sc = 1.f; }
        else              { dst = g_V + ((size_t)b * NC + (kg - 64)) * NPOS; sc = 1.f; }
        float4 v0 = make_float4(tf32r(acc[r][0] * sc), tf32r(acc[r][1] * sc),
                                tf32r(acc[r][2] * sc), tf32r(acc[r][3] * sc));
        float4 v1 = make_float4(tf32r(acc[r][4] * sc), tf32r(acc[r][5] * sc),
                                tf32r(acc[r][6] * sc), tf32r(acc[r][7] * sc));
        *(float4*)(dst + n0 + tx * 4)       = v0;
        *(float4*)(dst + n0 + 128 + tx * 4) = v1;
    }
}

// ---------------------------------------------------------------------------
// Flash attention, mma.sync tf32. CTA = 128 q x 256 d, key tile 64. 16 warps:
// mg = wid&3  -> 32 q-rows (2 m16 blocks), dc = wid>>2:
//   QK/exp phase: warp handles its 32 rows x 16 keys (kbase = dc*16)
//   PV phase:     warp handles its 32 rows x 64 d-cols (dstart = dc*64)
// ---------------------------------------------------------------------------
__global__ __launch_bounds__(THREADS) void attn_kernel(
    const float* __restrict__ x, float* __restrict__ out)
{
    extern __shared__ float S[];
    const uint32_t sb = s2u(S);

    const int t   = threadIdx.x;
    const int wid = t >> 5;
    const int lid = t & 31;
    const int gid = lid >> 2;     // 0..7
    const int tig = lid & 3;      // 0..3
    const int mg  = wid & 3;
    const int dcW = wid >> 2;     // 0..3
    const int rb  = mg * 32;
    const int kbase  = dcW * 16;
    const int dstart = dcW * 64;

    const int b  = blockIdx.y;
    const int q0 = blockIdx.x * QM;

    const float* Qg = g_Q + (size_t)b * NK * NPOS + q0;
    const float* Kg = g_K + (size_t)b * NK * NPOS;
    const float* Vg = g_V + (size_t)b * NC * NPOS;

    // ---- prologue: Q tile + K0 + V0, single commit group ----
    {
#pragma unroll
        for (int s = 0; s < 2; s++) {
            int i = t + s * THREADS;               // 0..1023
            int c = i >> 5, q4 = i & 31;
            cp16(sb + (OFF_Q + c * QS2) * 4 + q4 * 16, Qg + (size_t)c * NPOS + q4 * 4);
        }
        {
            int c = t >> 4, k4 = t & 15;           // 512 cp16
            cp16(sb + (OFF_K + c * KS2) * 4 + k4 * 16, Kg + (size_t)c * NPOS + k4 * 4);
        }
#pragma unroll
        for (int s = 0; s < 8; s++) {
            int i = t + s * THREADS;               // 0..4095
            int d = i >> 4, k4 = i & 15;
            cp16(sb + (OFF_V + d * VS2) * 4 + k4 * 16, Vg + (size_t)d * NPOS + k4 * 4);
        }
        CP_COMMIT();
    }

    float o[2][8][4];
#pragma unroll
    for (int r = 0; r < 2; r++)
#pragma unroll
        for (int n = 0; n < 8; n++)
#pragma unroll
            for (int c = 0; c < 4; c++) o[r][n][c] = 0.f;

    float lacc[2][2] = {{0.f, 0.f}, {0.f, 0.f}};

    for (int j = 0; j < NT; j++) {
        const int cur = j & 1;
        CP_WAIT(0);
        __syncthreads();

        // prefetch tile j+1 into the other buffer
        if (j + 1 < NT) {
            const int nb_ = (j + 1) & 1;
            const size_t koff = (size_t)(j + 1) * TK;
            {
                int c = t >> 4, k4 = t & 15;
                cp16(sb + (OFF_K + nb_ * KBUF + c * KS2) * 4 + k4 * 16,
                     Kg + (size_t)c * NPOS + koff + k4 * 4);
            }
#pragma unroll
            for (int s = 0; s < 8; s++) {
                int i = t + s * THREADS;
                int d = i >> 4, k4 = i & 15;
                cp16(sb + (OFF_V + nb_ * VBUF + d * VS2) * 4 + k4 * 16,
                     Vg + (size_t)d * NPOS + koff + k4 * 4);
            }
            CP_COMMIT();
        }

        // ---- QK^T + exp + P (all warps; 32 rows x 16 keys each) ----
        {
            const float* Ks = S + OFF_K + cur * KBUF;
            const float* Qs = S + OFF_Q;
            uint32_t kb0[2][4], kb1[2][4];
#pragma unroll
            for (int nb = 0; nb < 2; nb++) {
                const int key = kbase + nb * 8 + gid;
#pragma unroll
                for (int k = 0; k < 4; k++) {
                    kb0[nb][k] = fu(Ks[(k * 8 + tig) * KS2 + key]);
                    kb1[nb][k] = fu(Ks[(k * 8 + tig + 4) * KS2 + key]);
                }
            }
#pragma unroll
            for (int rbk = 0; rbk < 2; rbk++) {
                float s4[2][4];
#pragma unroll
                for (int nb = 0; nb < 2; nb++)
#pragma unroll
                    for (int c = 0; c < 4; c++) s4[nb][c] = 0.f;
                const int q = rb + rbk * 16 + gid;
#pragma unroll
                for (int k = 0; k < 4; k++) {
                    uint32_t qa[4];
                    qa[0] = fu(Qs[(k * 8 + tig) * QS2 + q]);
                    qa[1] = fu(Qs[(k * 8 + tig) * QS2 + q + 8]);
                    qa[2] = fu(Qs[(k * 8 + tig + 4) * QS2 + q]);
                    qa[3] = fu(Qs[(k * 8 + tig + 4) * QS2 + q + 8]);
                    mma8(s4[0], qa, kb0[0][k], kb1[0][k]);
                    mma8(s4[1], qa, kb0[1][k], kb1[1][k]);
                }
#pragma unroll
                for (int nb = 0; nb < 2; nb++) {
                    float e0 = ex2f(s4[nb][0]);
                    float e1 = ex2f(s4[nb][1]);
                    float e2 = ex2f(s4[nb][2]);
                    float e3 = ex2f(s4[nb][3]);
                    lacc[rbk][0] += e0 + e1;
                    lacc[rbk][1] += e2 + e3;
                    const int col = kbase + nb * 8 + 2 * tig;
                    *(float2*)&S[OFF_P + q * PS2 + col] =
                        make_float2(__uint_as_float(tf32u(e0)), __uint_as_float(tf32u(e1)));
                    *(float2*)&S[OFF_P + (q + 8) * PS2 + col] =
                        make_float2(__uint_as_float(tf32u(e2)), __uint_as_float(tf32u(e3)));
                }
            }
        }
        __syncthreads();

        // ---- O += P @ V (all warps; 32 rows x 64 d-cols each) ----
        {
            const float* Vs = S + OFF_V + cur * VBUF;
            const float* Ps = S + OFF_P;
#pragma unroll
            for (int k = 0; k < 8; k++) {
                uint32_t pa0[4], pa1[4];
                {
                    const int q = rb + gid;
                    pa0[0] = fu(Ps[q * PS2 + k * 8 + tig]);
                    pa0[1] = fu(Ps[(q + 8) * PS2 + k * 8 + tig]);
                    pa0[2] = fu(Ps[q * PS2 + k * 8 + tig + 4]);
                    pa0[3] = fu(Ps[(q + 8) * PS2 + k * 8 + tig + 4]);
                }
                {
                    const int q = rb + 16 + gid;
                    pa1[0] = fu(Ps[q * PS2 + k * 8 + tig]);
                    pa1[1] = fu(Ps[(q + 8) * PS2 + k * 8 + tig]);
                    pa1[2] = fu(Ps[q * PS2 + k * 8 + tig + 4]);
                    pa1[3] = fu(Ps[(q + 8) * PS2 + k * 8 + tig + 4]);
                }
#pragma unroll
                for (int n = 0; n < 8; n++) {
                    const int d0 = dstart + n * 8 + gid;
                    uint32_t vb0 = fu(Vs[d0 * VS2 + k * 8 + tig]);
                    uint32_t vb1 = fu(Vs[d0 * VS2 + k * 8 + tig + 4]);
                    mma8(o[0][n], pa0, vb0, vb1);
                    mma8(o[1][n], pa1, vb0, vb1);
                }
            }
        }
    }

    // ---- softmax denominators: quad-reduce, per-dc slots, then sum ----
#pragma unroll
    for (int rbk = 0; rbk < 2; rbk++)
#pragma unroll
        for (int h = 0; h < 2; h++) {
            float v = lacc[rbk][h];
            v += __shfl_xor_sync(0xffffffffu, v, 1);
            v += __shfl_xor_sync(0xffffffffu, v, 2);
            lacc[rbk][h] = v;
        }
    if (tig == 0) {
        S[OFF_L + dcW * QM + rb + gid]      = lacc[0][0];
        S[OFF_L + dcW * QM + rb + 8 + gid]  = lacc[0][1];
        S[OFF_L + dcW * QM + rb + 16 + gid] = lacc[1][0];
        S[OFF_L + dcW * QM + rb + 24 + gid] = lacc[1][1];
    }
    __syncthreads();

    float inv[2][2];
#pragma unroll
    for (int rbk = 0; rbk < 2; rbk++)
#pragma unroll
        for (int h = 0; h < 2; h++) {
            const int row = rb + rbk * 16 + h * 8 + gid;
            float s = S[OFF_L + row] + S[OFF_L + QM + row] +
                      S[OFF_L + 2 * QM + row] + S[OFF_L + 3 * QM + row];
            inv[rbk][h] = 1.f / s;
        }

    // ---- epilogue: O/l + residual, store [b][d][q] ----
#pragma unroll
    for (int rbk = 0; rbk < 2; rbk++) {
        const int q = q0 + rb + rbk * 16 + gid;
#pragma unroll
        for (int n = 0; n < 8; n++) {
            const int d0 = dstart + n * 8 + 2 * tig;
            size_t i0 = ((size_t)(b * NC + d0)) * NPOS + q;
            out[i0]            = o[rbk][n][0] * inv[rbk][0] + x[i0];
            out[i0 + NPOS]     = o[rbk][n][1] * inv[rbk][0] + x[i0 + NPOS];
            out[i0 + 8]        = o[rbk][n][2] * inv[rbk][1] + x[i0 + 8];
            out[i0 + NPOS + 8] = o[rbk][n][3] * inv[rbk][1] + x[i0 + NPOS + 8];
        }
    }
}

// ---------------------------------------------------------------------------
extern "C" void kernel_launch(void* const* d_in, const int* in_sizes, int n_in,
                              void* d_out, int out_size)
{
    const float* x  = (const float*)d_in[0];
    const float* w1 = (const float*)d_in[1];
    const float* w2 = (const float*)d_in[2];
    const float* w3 = (const float*)d_in[3];
    float* out = (float*)d_out;

    cudaFuncSetAttribute(attn_kernel, cudaFuncAttributeMaxDynamicSharedMemorySize,
                         SMEM_BYTES);

    dim3 gproj(NPOS / 256, 320 / 64, NB);   // (16, 5, 4)
    proj_kernel<<<gproj, 256>>>(x, w1, w2, w3);

    dim3 gattn(NPOS / QM, NB);              // (32, 4)
    attn_kernel<<<gattn, THREADS, SMEM_BYTES>>>(x, out);
}

// round 6
// speedup vs baseline: 6.2215x; 1.4139x over previous
#include <cuda_runtime.h>
#include <cuda_fp16.h>
#include <cstdint>

#define NB 4
#define NC 256
#define NK 32
#define NPOS 4096
#define QM 128
#define TK 128
#define NT (NPOS / TK)    // 32
#define THREADS 512
#define LOG2E 1.4426950408889634f

// ---------------- scratch (device globals; no allocs allowed) ---------------
__device__ __align__(128) __half g_Q[(size_t)NB * NPOS * NK];  // [b][n][32] (pre-scaled by log2e)
__device__ __align__(128) __half g_K[(size_t)NB * NPOS * NK];  // [b][n][32]
__device__ __align__(128) __half g_V[(size_t)NB * NC * NPOS];  // [b][d][n]
__device__ __align__(128) float  g_M[(size_t)NB * NPOS];       // row maxes (log2 units)

// ---------------- helpers ---------------------------------------------------
__device__ __forceinline__ uint32_t s2u(const void* p) {
    uint32_t a;
    asm("{ .reg .u64 t; cvta.to.shared.u64 t, %1; cvt.u32.u64 %0, t; }"
        : "=r"(a) : "l"(p));
    return a;
}
__device__ __forceinline__ void cp16(uint32_t s, const void* g) {
    asm volatile("cp.async.cg.shared.global [%0], [%1], 16;" :: "r"(s), "l"(g));
}
#define CP_COMMIT() asm volatile("cp.async.commit_group;" ::: "memory")
#define CP_WAIT(n)  asm volatile("cp.async.wait_group %0;" :: "n"(n) : "memory")

__device__ __forceinline__ float ex2f(float x) {
    float r; asm("ex2.approx.f32 %0, %1;" : "=f"(r) : "f"(x)); return r;
}

// m16n8k16 fp16 mma, fp32 accum: D += A*B
__device__ __forceinline__ void mma16(float* c, const uint32_t* a,
                                      uint32_t b0, uint32_t b1) {
    asm volatile(
        "mma.sync.aligned.m16n8k16.row.col.f32.f16.f16.f32 "
        "{%0,%1,%2,%3}, {%4,%5,%6,%7}, {%8,%9}, {%0,%1,%2,%3};"
        : "+f"(c[0]), "+f"(c[1]), "+f"(c[2]), "+f"(c[3])
        : "r"(a[0]), "r"(a[1]), "r"(a[2]), "r"(a[3]), "r"(b0), "r"(b1));
}
__device__ __forceinline__ uint32_t ldh2(const __half* p) {
    return *(const uint32_t*)p;
}

// ---- attn smem byte offsets ----
// Q  [128 q][40 c] half            (stride 80 B)
// K  2 x [128 key][40 c] half
// V  2 x [256 d][136 key] half     (stride 272 B)
// P  [128 q][136 key] half
// L  [4][128] float
#define QSH 40
#define KSH 40
#define VSH 136
#define PSH 136
#define SM_Q 0
#define SM_K (SM_Q + QM * QSH * 2)            // 10240
#define KBUFB (TK * KSH * 2)                   // 10240
#define SM_V (SM_K + 2 * KBUFB)                // 30720
#define VBUFB (NC * VSH * 2)                   // 69632
#define SM_P (SM_V + 2 * VBUFB)                // 169984
#define SM_L (SM_P + QM * PSH * 2)             // 204800
#define SMEM_BYTES (SM_L + 4 * QM * 4)         // 206848

// ---------------------------------------------------------------------------
// Projection: Wcat[320,256] @ x[b][256][4096], fp32 compute, fp16 outputs.
// blockIdx.y==0: rows 0..31 -> Q (*log2e, [b][n][c]), 32..63 -> K ([b][n][c])
// else: V rows -> [b][d][n].
// ---------------------------------------------------------------------------
__global__ __launch_bounds__(256) void proj_kernel(
    const float* __restrict__ x, const float* __restrict__ w1,
    const float* __restrict__ w2, const float* __restrict__ w3)
{
    const int n0 = blockIdx.x * 256;
    const int k0 = blockIdx.y * 64;
    const int b  = blockIdx.z;

    __shared__ float As[64 * 33];
    __shared__ float Bs[32 * 256];

    const int t  = threadIdx.x;
    const int ty = t >> 5;
    const int tx = t & 31;

    float acc[8][8];
#pragma unroll
    for (int r = 0; r < 8; r++)
#pragma unroll
        for (int c = 0; c < 8; c++) acc[r][c] = 0.f;

    const float* xb = x + (size_t)b * NC * NPOS;

    for (int c0 = 0; c0 < NC; c0 += 32) {
#pragma unroll
        for (int i = 0; i < 8; i++) {
            int idx = t + i * 256;
            int kk = idx >> 5, cc = idx & 31;
            int kg = k0 + kk;
            const float* wp; int row;
            if (kg < 32)      { wp = w1; row = kg; }
            else if (kg < 64) { wp = w2; row = kg - 32; }
            else              { wp = w3; row = kg - 64; }
            As[kk * 33 + cc] = wp[row * NC + c0 + cc];
        }
#pragma unroll
        for (int i = 0; i < 8; i++) {
            int idx = t + i * 256;
            int cc = idx >> 6, n4 = idx & 63;
            float4 v = *(const float4*)(xb + (size_t)(c0 + cc) * NPOS + n0 + n4 * 4);
            *(float4*)(Bs + cc * 256 + n4 * 4) = v;
        }
        __syncthreads();
#pragma unroll
        for (int cc = 0; cc < 32; cc++) {
            float a[8];
#pragma unroll
            for (int r = 0; r < 8; r++) a[r] = As[(ty * 8 + r) * 33 + cc];
            float4 b0 = *(const float4*)(Bs + cc * 256 + tx * 4);
            float4 b1 = *(const float4*)(Bs + cc * 256 + 128 + tx * 4);
#pragma unroll
            for (int r = 0; r < 8; r++) {
                acc[r][0] = fmaf(a[r], b0.x, acc[r][0]);
                acc[r][1] = fmaf(a[r], b0.y, acc[r][1]);
                acc[r][2] = fmaf(a[r], b0.z, acc[r][2]);
                acc[r][3] = fmaf(a[r], b0.w, acc[r][3]);
                acc[r][4] = fmaf(a[r], b1.x, acc[r][4]);
                acc[r][5] = fmaf(a[r], b1.y, acc[r][5]);
                acc[r][6] = fmaf(a[r], b1.z, acc[r][6]);
                acc[r][7] = fmaf(a[r], b1.w, acc[r][7]);
            }
        }
        __syncthreads();
    }

    if (blockIdx.y == 0) {
        // Q (ty<4) or K (ty>=4): store [b][n][c], 8 consecutive c per thread
        const bool isQ = (ty < 4);
        const float sc = isQ ? LOG2E : 1.f;
        __half* dst = (isQ ? g_Q : g_K) + (size_t)b * NPOS * NK;
        const int cbase = isQ ? ty * 8 : (ty - 4) * 8;
#pragma unroll
        for (int g = 0; g < 2; g++) {
#pragma unroll
            for (int cc = 0; cc < 4; cc++) {
                int n = n0 + g * 128 + tx * 4 + cc;
                __half2 h[4];
#pragma unroll
                for (int r2 = 0; r2 < 4; r2++)
                    h[r2] = __floats2half2_rn(acc[2 * r2][g * 4 + cc] * sc,
                                              acc[2 * r2 + 1][g * 4 + cc] * sc);
                *(uint4*)(dst + (size_t)n * NK + cbase) = *(uint4*)h;
            }
        }
    } else {
        // V: store [b][d][n], 8 consecutive n per thread (2x 8B)
#pragma unroll
        for (int r = 0; r < 8; r++) {
            int d = k0 + ty * 8 + r - 64;
            __half* dst = g_V + ((size_t)b * NC + d) * NPOS;
            __half2 p0 = __floats2half2_rn(acc[r][0], acc[r][1]);
            __half2 p1 = __floats2half2_rn(acc[r][2], acc[r][3]);
            __half2 p2 = __floats2half2_rn(acc[r][4], acc[r][5]);
            __half2 p3 = __floats2half2_rn(acc[r][6], acc[r][7]);
            *(__half2*)(dst + n0 + tx * 4)           = p0;
            *(__half2*)(dst + n0 + tx * 4 + 2)       = p1;
            *(__half2*)(dst + n0 + 128 + tx * 4)     = p2;
            *(__half2*)(dst + n0 + 128 + tx * 4 + 2) = p3;
        }
    }
}

// ---------------------------------------------------------------------------
// Row-max pre-pass: m[b][q] = max_key Q[q]·K[key] using the SAME fp16 mma as attn.
// grid (32, 4), 512 threads. Warp (mg = wid&3: 32 q) x (dcW = wid>>2: 32 keys/tile).
// ---------------------------------------------------------------------------
__global__ __launch_bounds__(512) void qkmax_kernel()
{
    __shared__ __align__(16) __half Qs[QM * QSH];
    __shared__ __align__(16) __half Ks[2 * TK * KSH];
    __shared__ float Mred[4 * QM];

    const uint32_t sbQ = s2u(Qs), sbK = s2u(Ks);
    const int t   = threadIdx.x;
    const int wid = t >> 5, lid = t & 31;
    const int gid = lid >> 2, tig = lid & 3;
    const int mg  = wid & 3, dcW = wid >> 2;
    const int rb  = mg * 32, kbase = dcW * 32;
    const int b   = blockIdx.y;
    const int q0  = blockIdx.x * QM;

    const __half* Qg = g_Q + ((size_t)b * NPOS + q0) * NK;
    const __half* Kg = g_K + (size_t)b * NPOS * NK;

    {   // Q: 512 cp16; K tile0: 512 cp16
        int q = t >> 2, c4 = t & 3;
        cp16(sbQ + q * (QSH * 2) + c4 * 16, Qg + (size_t)q * NK + c4 * 8);
        cp16(sbK + q * (KSH * 2) + c4 * 16, Kg + (size_t)q * NK + c4 * 8);
        CP_COMMIT();
    }

    float mx0[2] = {-1e30f, -1e30f}, mx1[2] = {-1e30f, -1e30f};

    for (int j = 0; j < NT; j++) {
        const int cur = j & 1;
        CP_WAIT(0);
        __syncthreads();
        if (j + 1 < NT) {
            int key = t >> 2, c4 = t & 3;
            cp16(sbK + ((1 - cur) * TK + key) * (KSH * 2) + c4 * 16,
                 Kg + ((size_t)(j + 1) * TK + key) * NK + c4 * 8);
            CP_COMMIT();
        }
        const __half* Kb = Ks + cur * TK * KSH;
#pragma unroll
        for (int rbk = 0; rbk < 2; rbk++) {
            const int q = rb + rbk * 16 + gid;
            uint32_t qa[2][4];
#pragma unroll
            for (int kk = 0; kk < 2; kk++) {
                qa[kk][0] = ldh2(&Qs[q * QSH + kk * 16 + 2 * tig]);
                qa[kk][1] = ldh2(&Qs[(q + 8) * QSH + kk * 16 + 2 * tig]);
                qa[kk][2] = ldh2(&Qs[q * QSH + kk * 16 + 8 + 2 * tig]);
                qa[kk][3] = ldh2(&Qs[(q + 8) * QSH + kk * 16 + 8 + 2 * tig]);
            }
#pragma unroll
            for (int nb = 0; nb < 4; nb++) {
                const int key = kbase + nb * 8 + gid;
                float s4[4] = {0.f, 0.f, 0.f, 0.f};
#pragma unroll
                for (int kk = 0; kk < 2; kk++) {
                    uint32_t b0 = ldh2(&Kb[key * KSH + kk * 16 + 2 * tig]);
                    uint32_t b1 = ldh2(&Kb[key * KSH + kk * 16 + 8 + 2 * tig]);
                    mma16(s4, qa[kk], b0, b1);
                }
                mx0[rbk] = fmaxf(mx0[rbk], fmaxf(s4[0], s4[1]));
                mx1[rbk] = fmaxf(mx1[rbk], fmaxf(s4[2], s4[3]));
            }
        }
    }

#pragma unroll
    for (int rbk = 0; rbk < 2; rbk++) {
        mx0[rbk] = fmaxf(mx0[rbk], __shfl_xor_sync(0xffffffffu, mx0[rbk], 1));
        mx0[rbk] = fmaxf(mx0[rbk], __shfl_xor_sync(0xffffffffu, mx0[rbk], 2));
        mx1[rbk] = fmaxf(mx1[rbk], __shfl_xor_sync(0xffffffffu, mx1[rbk], 1));
        mx1[rbk] = fmaxf(mx1[rbk], __shfl_xor_sync(0xffffffffu, mx1[rbk], 2));
    }
    if (tig == 0) {
        Mred[dcW * QM + rb + gid]      = mx0[0];
        Mred[dcW * QM + rb + 8 + gid]  = mx1[0];
        Mred[dcW * QM + rb + 16 + gid] = mx0[1];
        Mred[dcW * QM + rb + 24 + gid] = mx1[1];
    }
    __syncthreads();
    if (t < QM) {
        float m = fmaxf(fmaxf(Mred[t], Mred[QM + t]),
                        fmaxf(Mred[2 * QM + t], Mred[3 * QM + t]));
        g_M[(size_t)b * NPOS + q0 + t] = m;
    }
}

// ---------------------------------------------------------------------------
// fp16 flash attention with precomputed row maxes. CTA = 128 q x 256 d,
// key tile 128. 16 warps: mg = wid&3 (32 q), dcW = wid>>2:
//   QK/exp: 32 q x 32 keys per warp.  PV: 32 q x 64 d per warp.
// ---------------------------------------------------------------------------
__global__ __launch_bounds__(THREADS) void attn_kernel(
    const float* __restrict__ x, float* __restrict__ out)
{
    extern __shared__ __align__(16) char sm[];
    const uint32_t sb = s2u(sm);
    const __half* Qs = (const __half*)(sm + SM_Q);
    __half* Ps       = (__half*)(sm + SM_P);
    float* SL        = (float*)(sm + SM_L);

    const int t   = threadIdx.x;
    const int wid = t >> 5, lid = t & 31;
    const int gid = lid >> 2, tig = lid & 3;
    const int mg  = wid & 3, dcW = wid >> 2;
    const int rb  = mg * 32;
    const int kbase  = dcW * 32;
    const int dstart = dcW * 64;
    const int b  = blockIdx.y;
    const int q0 = blockIdx.x * QM;

    const __half* Qg = g_Q + ((size_t)b * NPOS + q0) * NK;
    const __half* Kg = g_K + (size_t)b * NPOS * NK;
    const __half* Vg = g_V + (size_t)b * NC * NPOS;

    // row maxes for this thread's 4 rows
    const float* Mg = g_M + (size_t)b * NPOS + q0;
    float m0[2], m1[2];
    m0[0] = Mg[rb + gid];      m1[0] = Mg[rb + 8 + gid];
    m0[1] = Mg[rb + 16 + gid]; m1[1] = Mg[rb + 24 + gid];

    // ---- prologue: Q + K0 + V0 ----
    {
        int q = t >> 2, c4 = t & 3;
        cp16(sb + SM_Q + q * (QSH * 2) + c4 * 16, Qg + (size_t)q * NK + c4 * 8);
        cp16(sb + SM_K + q * (KSH * 2) + c4 * 16, Kg + (size_t)q * NK + c4 * 8);
#pragma unroll
        for (int s = 0; s < 8; s++) {
            int i = t + s * THREADS;            // 0..4095
            int d = i >> 4, k4 = i & 15;
            cp16(sb + SM_V + d * (VSH * 2) + k4 * 16, Vg + (size_t)d * NPOS + k4 * 8);
        }
        CP_COMMIT();
    }

    float o[2][8][4];
#pragma unroll
    for (int r = 0; r < 2; r++)
#pragma unroll
        for (int n = 0; n < 8; n++)
#pragma unroll
            for (int c = 0; c < 4; c++) o[r][n][c] = 0.f;

    float lacc[2][2] = {{0.f, 0.f}, {0.f, 0.f}};

    for (int j = 0; j < NT; j++) {
        const int cur = j & 1;
        CP_WAIT(0);
        __syncthreads();

        if (j + 1 < NT) {
            const size_t koff = (size_t)(j + 1) * TK;
            int q = t >> 2, c4 = t & 3;
            cp16(sb + SM_K + ((1 - cur) * TK + q) * (KSH * 2) + c4 * 16,
                 Kg + (koff + q) * NK + c4 * 8);
#pragma unroll
            for (int s = 0; s < 8; s++) {
                int i = t + s * THREADS;
                int d = i >> 4, k4 = i & 15;
                cp16(sb + SM_V + (1 - cur) * VBUFB + d * (VSH * 2) + k4 * 16,
                     Vg + (size_t)d * NPOS + koff + k4 * 8);
            }
            CP_COMMIT();
        }

        // ---- phase A: S = Q K^T, e = 2^(s-m), P -> smem ----
        {
            const __half* Kb = (const __half*)(sm + SM_K) + cur * TK * KSH;
#pragma unroll
            for (int rbk = 0; rbk < 2; rbk++) {
                const int q = rb + rbk * 16 + gid;
                uint32_t qa[2][4];
#pragma unroll
                for (int kk = 0; kk < 2; kk++) {
                    qa[kk][0] = ldh2(&Qs[q * QSH + kk * 16 + 2 * tig]);
                    qa[kk][1] = ldh2(&Qs[(q + 8) * QSH + kk * 16 + 2 * tig]);
                    qa[kk][2] = ldh2(&Qs[q * QSH + kk * 16 + 8 + 2 * tig]);
                    qa[kk][3] = ldh2(&Qs[(q + 8) * QSH + kk * 16 + 8 + 2 * tig]);
                }
#pragma unroll
                for (int nb = 0; nb < 4; nb++) {
                    const int key = kbase + nb * 8 + gid;
                    float s4[4] = {0.f, 0.f, 0.f, 0.f};
#pragma unroll
                    for (int kk = 0; kk < 2; kk++) {
                        uint32_t b0 = ldh2(&Kb[key * KSH + kk * 16 + 2 * tig]);
                        uint32_t b1 = ldh2(&Kb[key * KSH + kk * 16 + 8 + 2 * tig]);
                        mma16(s4, qa[kk], b0, b1);
                    }
                    float e0 = ex2f(s4[0] - m0[rbk]);
                    float e1 = ex2f(s4[1] - m0[rbk]);
                    float e2 = ex2f(s4[2] - m1[rbk]);
                    float e3 = ex2f(s4[3] - m1[rbk]);
                    lacc[rbk][0] += e0 + e1;
                    lacc[rbk][1] += e2 + e3;
                    const int col = kbase + nb * 8 + 2 * tig;
                    *(__half2*)&Ps[q * PSH + col]       = __floats2half2_rn(e0, e1);
                    *(__half2*)&Ps[(q + 8) * PSH + col] = __floats2half2_rn(e2, e3);
                }
            }
        }
        __syncthreads();

        // ---- phase B: O += P @ V ----
        {
            const __half* Vs = (const __half*)(sm + SM_V) + cur * NC * VSH;
#pragma unroll
            for (int kk = 0; kk < 8; kk++) {
                const int base = kk * 16;
                uint32_t pa0[4], pa1[4];
                {
                    const int q = rb + gid;
                    pa0[0] = ldh2(&Ps[q * PSH + base + 2 * tig]);
                    pa0[1] = ldh2(&Ps[(q + 8) * PSH + base + 2 * tig]);
                    pa0[2] = ldh2(&Ps[q * PSH + base + 8 + 2 * tig]);
                    pa0[3] = ldh2(&Ps[(q + 8) * PSH + base + 8 + 2 * tig]);
                }
                {
                    const int q = rb + 16 + gid;
                    pa1[0] = ldh2(&Ps[q * PSH + base + 2 * tig]);
                    pa1[1] = ldh2(&Ps[(q + 8) * PSH + base + 2 * tig]);
                    pa1[2] = ldh2(&Ps[q * PSH + base + 8 + 2 * tig]);
                    pa1[3] = ldh2(&Ps[(q + 8) * PSH + base + 8 + 2 * tig]);
                }
#pragma unroll
                for (int n = 0; n < 8; n++) {
                    const int d = dstart + n * 8 + gid;
                    uint32_t vb0 = ldh2(&Vs[d * VSH + base + 2 * tig]);
                    uint32_t vb1 = ldh2(&Vs[d * VSH + base + 8 + 2 * tig]);
                    mma16(o[0][n], pa0, vb0, vb1);
                    mma16(o[1][n], pa1, vb0, vb1);
                }
            }
        }
    }

    // ---- denominators: quad-reduce, per-dc slots, then sum ----
#pragma unroll
    for (int rbk = 0; rbk < 2; rbk++)
#pragma unroll
        for (int h = 0; h < 2; h++) {
            float v = lacc[rbk][h];
            v += __shfl_xor_sync(0xffffffffu, v, 1);
            v += __shfl_xor_sync(0xffffffffu, v, 2);
            lacc[rbk][h] = v;
        }
    if (tig == 0) {
        SL[dcW * QM + rb + gid]      = lacc[0][0];
        SL[dcW * QM + rb + 8 + gid]  = lacc[0][1];
        SL[dcW * QM + rb + 16 + gid] = lacc[1][0];
        SL[dcW * QM + rb + 24 + gid] = lacc[1][1];
    }
    __syncthreads();

    float inv[2][2];
#pragma unroll
    for (int rbk = 0; rbk < 2; rbk++)
#pragma unroll
        for (int h = 0; h < 2; h++) {
            const int row = rb + rbk * 16 + h * 8 + gid;
            float s = SL[row] + SL[QM + row] + SL[2 * QM + row] + SL[3 * QM + row];
            inv[rbk][h] = 1.f / s;
        }

    // ---- epilogue: O/l + residual, store [b][d][q] fp32 ----
#pragma unroll
    for (int rbk = 0; rbk < 2; rbk++) {
        const int q = q0 + rb + rbk * 16 + gid;
#pragma unroll
        for (int n = 0; n < 8; n++) {
            const int d0 = dstart + n * 8 + 2 * tig;
            size_t i0 = ((size_t)(b * NC + d0)) * NPOS + q;
            out[i0]            = o[rbk][n][0] * inv[rbk][0] + x[i0];
            out[i0 + NPOS]     = o[rbk][n][1] * inv[rbk][0] + x[i0 + NPOS];
            out[i0 + 8]        = o[rbk][n][2] * inv[rbk][1] + x[i0 + 8];
            out[i0 + NPOS + 8] = o[rbk][n][3] * inv[rbk][1] + x[i0 + NPOS + 8];
        }
    }
}

// ---------------------------------------------------------------------------
extern "C" void kernel_launch(void* const* d_in, const int* in_sizes, int n_in,
                              void* d_out, int out_size)
{
    const float* x  = (const float*)d_in[0];
    const float* w1 = (const float*)d_in[1];
    const float* w2 = (const float*)d_in[2];
    const float* w3 = (const float*)d_in[3];
    float* out = (float*)d_out;

    cudaFuncSetAttribute(attn_kernel, cudaFuncAttributeMaxDynamicSharedMemorySize,
                         SMEM_BYTES);

    dim3 gproj(NPOS / 256, 320 / 64, NB);   // (16, 5, 4)
    proj_kernel<<<gproj, 256>>>(x, w1, w2, w3);

    dim3 gqk(NPOS / QM, NB);                // (32, 4)
    qkmax_kernel<<<gqk, 512>>>();

    dim3 gattn(NPOS / QM, NB);              // (32, 4)
    attn_kernel<<<gattn, THREADS, SMEM_BYTES>>>(x, out);
}

// round 7
// speedup vs baseline: 7.1049x; 1.1420x over previous
#include <cuda_runtime.h>
#include <cuda_fp16.h>
#include <cstdint>

#define NB 4
#define NC 256
#define NK 32
#define NPOS 4096
#define QM 128
#define TK 128
#define NT (NPOS / TK)    // 32
#define THREADS 512
#define LOG2E 1.4426950408889634f

// ---------------- scratch (device globals; no allocs allowed) ---------------
__device__ __align__(128) __half g_Q[(size_t)NB * NPOS * NK];  // [b][n][32] (pre-scaled by log2e)
__device__ __align__(128) __half g_K[(size_t)NB * NPOS * NK];  // [b][n][32]
__device__ __align__(128) __half g_V[(size_t)NB * NC * NPOS];  // [b][d][n]
__device__ __align__(128) float  g_M[(size_t)NB * NPOS];       // row maxes (log2 units)

// ---------------- helpers ---------------------------------------------------
__device__ __forceinline__ uint32_t s2u(const void* p) {
    uint32_t a;
    asm("{ .reg .u64 t; cvta.to.shared.u64 t, %1; cvt.u32.u64 %0, t; }"
        : "=r"(a) : "l"(p));
    return a;
}
__device__ __forceinline__ void cp16(uint32_t s, const void* g) {
    asm volatile("cp.async.cg.shared.global [%0], [%1], 16;" :: "r"(s), "l"(g));
}
#define CP_COMMIT() asm volatile("cp.async.commit_group;" ::: "memory")
#define CP_WAIT(n)  asm volatile("cp.async.wait_group %0;" :: "n"(n) : "memory")

__device__ __forceinline__ float ex2f(float x) {
    float r; asm("ex2.approx.f32 %0, %1;" : "=f"(r) : "f"(x)); return r;
}
// m16n8k16 fp16 mma, fp32 accum
__device__ __forceinline__ void mma16(float* c, const uint32_t* a,
                                      uint32_t b0, uint32_t b1) {
    asm volatile(
        "mma.sync.aligned.m16n8k16.row.col.f32.f16.f16.f32 "
        "{%0,%1,%2,%3}, {%4,%5,%6,%7}, {%8,%9}, {%0,%1,%2,%3};"
        : "+f"(c[0]), "+f"(c[1]), "+f"(c[2]), "+f"(c[3])
        : "r"(a[0]), "r"(a[1]), "r"(a[2]), "r"(a[3]), "r"(b0), "r"(b1));
}
__device__ __forceinline__ void ldsm4(uint32_t* r, uint32_t saddr) {
    asm volatile("ldmatrix.sync.aligned.m8n8.x4.shared.b16 {%0,%1,%2,%3}, [%4];"
        : "=r"(r[0]), "=r"(r[1]), "=r"(r[2]), "=r"(r[3]) : "r"(saddr));
}

// ---- attn smem byte offsets ----
#define QSH 40
#define KSH 40
#define VSH 136
#define PSH 136
#define SM_Q 0
#define SM_K (SM_Q + QM * QSH * 2)            // 10240
#define KBUFB (TK * KSH * 2)                   // 10240
#define SM_V (SM_K + 2 * KBUFB)                // 30720
#define VBUFB (NC * VSH * 2)                   // 69632
#define SM_P (SM_V + 2 * VBUFB)                // 169984
#define SM_L (SM_P + QM * PSH * 2)             // 204800
#define SMEM_BYTES (SM_L + 4 * QM * 4)         // 206848

// ---- proj smem ----
#define PAS 36
#define PROJ_SMEM ((2 * 64 * PAS + 2 * 32 * 256) * 4)   // 83968

// ---------------------------------------------------------------------------
// Projection with cp.async double buffering, 2 CTAs/SM.
// ---------------------------------------------------------------------------
__global__ __launch_bounds__(256, 2) void proj_kernel(
    const float* __restrict__ x, const float* __restrict__ w1,
    const float* __restrict__ w2, const float* __restrict__ w3)
{
    extern __shared__ float PS[];
    float* As = PS;                    // [2][64*36]
    float* Bs = PS + 2 * 64 * PAS;     // [2][32*256]
    const uint32_t sA = s2u(As), sB = s2u(Bs);

    const int n0 = blockIdx.x * 256;
    const int k0 = blockIdx.y * 64;
    const int b  = blockIdx.z;
    const int t  = threadIdx.x;
    const int ty = t >> 5;
    const int tx = t & 31;

    const float* xb = x + (size_t)b * NC * NPOS;

    auto prefetch = [&](int c0, int bi) {
#pragma unroll
        for (int i = 0; i < 2; i++) {
            int idx = t + i * 256;               // 0..511
            int row = idx >> 3, c4 = idx & 7;
            int kg = k0 + row;
            const float* wp; int wr;
            if (kg < 32)      { wp = w1; wr = kg; }
            else if (kg < 64) { wp = w2; wr = kg - 32; }
            else              { wp = w3; wr = kg - 64; }
            cp16(sA + (bi * 64 * PAS + row * PAS + c4 * 4) * 4,
                 wp + wr * NC + c0 + c4 * 4);
        }
#pragma unroll
        for (int i = 0; i < 8; i++) {
            int idx = t + i * 256;               // 0..2047
            int cc = idx >> 6, n4 = idx & 63;
            cp16(sB + (bi * 32 * 256 + cc * 256 + n4 * 4) * 4,
                 xb + (size_t)(c0 + cc) * NPOS + n0 + n4 * 4);
        }
    };

    prefetch(0, 0);
    CP_COMMIT();

    float acc[8][8];
#pragma unroll
    for (int r = 0; r < 8; r++)
#pragma unroll
        for (int c = 0; c < 8; c++) acc[r][c] = 0.f;

    for (int c0 = 0; c0 < NC; c0 += 32) {
        const int bi = (c0 >> 5) & 1;
        CP_WAIT(0);
        __syncthreads();
        if (c0 + 32 < NC) { prefetch(c0 + 32, bi ^ 1); CP_COMMIT(); }

        const float* A  = As + bi * 64 * PAS;
        const float* Bb = Bs + bi * 32 * 256;
#pragma unroll
        for (int cc = 0; cc < 32; cc++) {
            float a[8];
#pragma unroll
            for (int r = 0; r < 8; r++) a[r] = A[(ty * 8 + r) * PAS + cc];
            float4 b0 = *(const float4*)(Bb + cc * 256 + tx * 4);
            float4 b1 = *(const float4*)(Bb + cc * 256 + 128 + tx * 4);
#pragma unroll
            for (int r = 0; r < 8; r++) {
                acc[r][0] = fmaf(a[r], b0.x, acc[r][0]);
                acc[r][1] = fmaf(a[r], b0.y, acc[r][1]);
                acc[r][2] = fmaf(a[r], b0.z, acc[r][2]);
                acc[r][3] = fmaf(a[r], b0.w, acc[r][3]);
                acc[r][4] = fmaf(a[r], b1.x, acc[r][4]);
                acc[r][5] = fmaf(a[r], b1.y, acc[r][5]);
                acc[r][6] = fmaf(a[r], b1.z, acc[r][6]);
                acc[r][7] = fmaf(a[r], b1.w, acc[r][7]);
            }
        }
    }

    if (blockIdx.y == 0) {
        const bool isQ = (ty < 4);
        const float sc = isQ ? LOG2E : 1.f;
        __half* dst = (isQ ? g_Q : g_K) + (size_t)b * NPOS * NK;
        const int cbase = isQ ? ty * 8 : (ty - 4) * 8;
#pragma unroll
        for (int g = 0; g < 2; g++) {
#pragma unroll
            for (int cc = 0; cc < 4; cc++) {
                int n = n0 + g * 128 + tx * 4 + cc;
                __half2 h[4];
#pragma unroll
                for (int r2 = 0; r2 < 4; r2++)
                    h[r2] = __floats2half2_rn(acc[2 * r2][g * 4 + cc] * sc,
                                              acc[2 * r2 + 1][g * 4 + cc] * sc);
                *(uint4*)(dst + (size_t)n * NK + cbase) = *(uint4*)h;
            }
        }
    } else {
#pragma unroll
        for (int r = 0; r < 8; r++) {
            int d = k0 + ty * 8 + r - 64;
            __half* dst = g_V + ((size_t)b * NC + d) * NPOS;
            *(__half2*)(dst + n0 + tx * 4)           = __floats2half2_rn(acc[r][0], acc[r][1]);
            *(__half2*)(dst + n0 + tx * 4 + 2)       = __floats2half2_rn(acc[r][2], acc[r][3]);
            *(__half2*)(dst + n0 + 128 + tx * 4)     = __floats2half2_rn(acc[r][4], acc[r][5]);
            *(__half2*)(dst + n0 + 128 + tx * 4 + 2) = __floats2half2_rn(acc[r][6], acc[r][7]);
        }
    }
}

// ---------------------------------------------------------------------------
// Row-max pre-pass with ldmatrix fragment loads.
// ---------------------------------------------------------------------------
__global__ __launch_bounds__(512) void qkmax_kernel()
{
    __shared__ __align__(16) __half Qs[QM * QSH];
    __shared__ __align__(16) __half Ks[2 * TK * KSH];
    __shared__ float Mred[4 * QM];

    const uint32_t sbQ = s2u(Qs), sbK = s2u(Ks);
    const int t   = threadIdx.x;
    const int wid = t >> 5, lid = t & 31;
    const int mg  = wid & 3, dcW = wid >> 2;
    const int rb  = mg * 32, kbase = dcW * 32;
    const int b   = blockIdx.y;
    const int q0  = blockIdx.x * QM;

    const int arow  = lid & 15;
    const int acolh = (lid >> 4) << 3;
    const int brow  = ((lid >> 4) << 3) | (lid & 7);
    const int bcolh = ((lid >> 3) & 1) << 3;

    const __half* Qg = g_Q + ((size_t)b * NPOS + q0) * NK;
    const __half* Kg = g_K + (size_t)b * NPOS * NK;

    {
        int q = t >> 2, c4 = t & 3;
        cp16(sbQ + q * (QSH * 2) + c4 * 16, Qg + (size_t)q * NK + c4 * 8);
        cp16(sbK + q * (KSH * 2) + c4 * 16, Kg + (size_t)q * NK + c4 * 8);
        CP_COMMIT();
    }

    float mx0[2] = {-1e30f, -1e30f}, mx1[2] = {-1e30f, -1e30f};
    uint32_t qf[2][2][4];
    bool qloaded = false;

    for (int j = 0; j < NT; j++) {
        const int cur = j & 1;
        CP_WAIT(0);
        __syncthreads();
        if (!qloaded) {
            qloaded = true;
#pragma unroll
            for (int rbk = 0; rbk < 2; rbk++)
#pragma unroll
                for (int kk = 0; kk < 2; kk++)
                    ldsm4(qf[rbk][kk],
                          sbQ + ((rb + rbk * 16 + arow) * QSH + kk * 16 + acolh) * 2);
        }
        if (j + 1 < NT) {
            int key = t >> 2, c4 = t & 3;
            cp16(sbK + ((1 - cur) * TK + key) * (KSH * 2) + c4 * 16,
                 Kg + ((size_t)(j + 1) * TK + key) * NK + c4 * 8);
            CP_COMMIT();
        }
        const uint32_t kbB = sbK + cur * TK * (KSH * 2);
#pragma unroll
        for (int nbp = 0; nbp < 2; nbp++) {
            uint32_t kf[2][4];
#pragma unroll
            for (int kk = 0; kk < 2; kk++)
                ldsm4(kf[kk], kbB + ((kbase + nbp * 16 + brow) * KSH + kk * 16 + bcolh) * 2);
#pragma unroll
            for (int rbk = 0; rbk < 2; rbk++) {
                float s4[2][4] = {{0.f,0.f,0.f,0.f},{0.f,0.f,0.f,0.f}};
#pragma unroll
                for (int kk = 0; kk < 2; kk++) {
                    mma16(s4[0], qf[rbk][kk], kf[kk][0], kf[kk][1]);
                    mma16(s4[1], qf[rbk][kk], kf[kk][2], kf[kk][3]);
                }
#pragma unroll
                for (int nb2 = 0; nb2 < 2; nb2++) {
                    mx0[rbk] = fmaxf(mx0[rbk], fmaxf(s4[nb2][0], s4[nb2][1]));
                    mx1[rbk] = fmaxf(mx1[rbk], fmaxf(s4[nb2][2], s4[nb2][3]));
                }
            }
        }
    }

    const int gid = lid >> 2, tig = lid & 3;
#pragma unroll
    for (int rbk = 0; rbk < 2; rbk++) {
        mx0[rbk] = fmaxf(mx0[rbk], __shfl_xor_sync(0xffffffffu, mx0[rbk], 1));
        mx0[rbk] = fmaxf(mx0[rbk], __shfl_xor_sync(0xffffffffu, mx0[rbk], 2));
        mx1[rbk] = fmaxf(mx1[rbk], __shfl_xor_sync(0xffffffffu, mx1[rbk], 1));
        mx1[rbk] = fmaxf(mx1[rbk], __shfl_xor_sync(0xffffffffu, mx1[rbk], 2));
    }
    if (tig == 0) {
        Mred[dcW * QM + rb + gid]      = mx0[0];
        Mred[dcW * QM + rb + 8 + gid]  = mx1[0];
        Mred[dcW * QM + rb + 16 + gid] = mx0[1];
        Mred[dcW * QM + rb + 24 + gid] = mx1[1];
    }
    __syncthreads();
    if (t < QM) {
        float m = fmaxf(fmaxf(Mred[t], Mred[QM + t]),
                        fmaxf(Mred[2 * QM + t], Mred[3 * QM + t]));
        g_M[(size_t)b * NPOS + q0 + t] = m;
    }
}

// ---------------------------------------------------------------------------
// fp16 flash attention, ldmatrix fragment loads.
// ---------------------------------------------------------------------------
__global__ __launch_bounds__(THREADS) void attn_kernel(
    const float* __restrict__ x, float* __restrict__ out)
{
    extern __shared__ __align__(16) char sm[];
    const uint32_t sb = s2u(sm);
    __half* Ps = (__half*)(sm + SM_P);
    float* SL  = (float*)(sm + SM_L);

    const int t   = threadIdx.x;
    const int wid = t >> 5, lid = t & 31;
    const int gid = lid >> 2, tig = lid & 3;
    const int mg  = wid & 3, dcW = wid >> 2;
    const int rb  = mg * 32;
    const int kbase  = dcW * 32;
    const int dstart = dcW * 64;
    const int b  = blockIdx.y;
    const int q0 = blockIdx.x * QM;

    const int arow  = lid & 15;
    const int acolh = (lid >> 4) << 3;
    const int brow  = ((lid >> 4) << 3) | (lid & 7);
    const int bcolh = ((lid >> 3) & 1) << 3;

    const __half* Qg = g_Q + ((size_t)b * NPOS + q0) * NK;
    const __half* Kg = g_K + (size_t)b * NPOS * NK;
    const __half* Vg = g_V + (size_t)b * NC * NPOS;

    const float* Mg = g_M + (size_t)b * NPOS + q0;
    float m0[2], m1[2];
    m0[0] = Mg[rb + gid];      m1[0] = Mg[rb + 8 + gid];
    m0[1] = Mg[rb + 16 + gid]; m1[1] = Mg[rb + 24 + gid];

    {
        int q = t >> 2, c4 = t & 3;
        cp16(sb + SM_Q + q * (QSH * 2) + c4 * 16, Qg + (size_t)q * NK + c4 * 8);
        cp16(sb + SM_K + q * (KSH * 2) + c4 * 16, Kg + (size_t)q * NK + c4 * 8);
#pragma unroll
        for (int s = 0; s < 8; s++) {
            int i = t + s * THREADS;
            int d = i >> 4, k4 = i & 15;
            cp16(sb + SM_V + d * (VSH * 2) + k4 * 16, Vg + (size_t)d * NPOS + k4 * 8);
        }
        CP_COMMIT();
    }

    float o[2][8][4];
#pragma unroll
    for (int r = 0; r < 2; r++)
#pragma unroll
        for (int n = 0; n < 8; n++)
#pragma unroll
            for (int c = 0; c < 4; c++) o[r][n][c] = 0.f;

    float lacc[2][2] = {{0.f, 0.f}, {0.f, 0.f}};
    uint32_t qf[2][2][4];
    bool qloaded = false;

    for (int j = 0; j < NT; j++) {
        const int cur = j & 1;
        CP_WAIT(0);
        __syncthreads();

        if (!qloaded) {
            qloaded = true;
#pragma unroll
            for (int rbk = 0; rbk < 2; rbk++)
#pragma unroll
                for (int kk = 0; kk < 2; kk++)
                    ldsm4(qf[rbk][kk],
                          sb + SM_Q + ((rb + rbk * 16 + arow) * QSH + kk * 16 + acolh) * 2);
        }

        if (j + 1 < NT) {
            const size_t koff = (size_t)(j + 1) * TK;
            int q = t >> 2, c4 = t & 3;
            cp16(sb + SM_K + ((1 - cur) * TK + q) * (KSH * 2) + c4 * 16,
                 Kg + (koff + q) * NK + c4 * 8);
#pragma unroll
            for (int s = 0; s < 8; s++) {
                int i = t + s * THREADS;
                int d = i >> 4, k4 = i & 15;
                cp16(sb + SM_V + (1 - cur) * VBUFB + d * (VSH * 2) + k4 * 16,
                     Vg + (size_t)d * NPOS + koff + k4 * 8);
            }
            CP_COMMIT();
        }

        // ---- phase A: S = Q K^T, e = 2^(s-m), P -> smem ----
        {
            const uint32_t kbB = sb + SM_K + cur * KBUFB;
#pragma unroll
            for (int nbp = 0; nbp < 2; nbp++) {
                uint32_t kf[2][4];
#pragma unroll
                for (int kk = 0; kk < 2; kk++)
                    ldsm4(kf[kk],
                          kbB + ((kbase + nbp * 16 + brow) * KSH + kk * 16 + bcolh) * 2);
#pragma unroll
                for (int rbk = 0; rbk < 2; rbk++) {
                    float s4[2][4] = {{0.f,0.f,0.f,0.f},{0.f,0.f,0.f,0.f}};
#pragma unroll
                    for (int kk = 0; kk < 2; kk++) {
                        mma16(s4[0], qf[rbk][kk], kf[kk][0], kf[kk][1]);
                        mma16(s4[1], qf[rbk][kk], kf[kk][2], kf[kk][3]);
                    }
                    const int q = rb + rbk * 16 + gid;
#pragma unroll
                    for (int nb2 = 0; nb2 < 2; nb2++) {
                        float e0 = ex2f(s4[nb2][0] - m0[rbk]);
                        float e1 = ex2f(s4[nb2][1] - m0[rbk]);
                        float e2 = ex2f(s4[nb2][2] - m1[rbk]);
                        float e3 = ex2f(s4[nb2][3] - m1[rbk]);
                        lacc[rbk][0] += e0 + e1;
                        lacc[rbk][1] += e2 + e3;
                        const int col = kbase + nbp * 16 + nb2 * 8 + 2 * tig;
                        *(__half2*)&Ps[q * PSH + col]       = __floats2half2_rn(e0, e1);
                        *(__half2*)&Ps[(q + 8) * PSH + col] = __floats2half2_rn(e2, e3);
                    }
                }
            }
        }
        __syncthreads();

        // ---- phase B: O += P @ V ----
        {
            const uint32_t vbB = sb + SM_V + cur * VBUFB;
#pragma unroll
            for (int kk = 0; kk < 8; kk++) {
                uint32_t pf[2][4];
#pragma unroll
                for (int rbk = 0; rbk < 2; rbk++)
                    ldsm4(pf[rbk],
                          sb + SM_P + ((rb + rbk * 16 + arow) * PSH + kk * 16 + acolh) * 2);
#pragma unroll
                for (int dp = 0; dp < 4; dp++) {
                    uint32_t vf[4];
                    ldsm4(vf, vbB + ((dstart + dp * 16 + brow) * VSH + kk * 16 + bcolh) * 2);
                    mma16(o[0][2 * dp],     pf[0], vf[0], vf[1]);
                    mma16(o[0][2 * dp + 1], pf[0], vf[2], vf[3]);
                    mma16(o[1][2 * dp],     pf[1], vf[0], vf[1]);
                    mma16(o[1][2 * dp + 1], pf[1], vf[2], vf[3]);
                }
            }
        }
    }

    // ---- denominators ----
#pragma unroll
    for (int rbk = 0; rbk < 2; rbk++)
#pragma unroll
        for (int h = 0; h < 2; h++) {
            float v = lacc[rbk][h];
            v += __shfl_xor_sync(0xffffffffu, v, 1);
            v += __shfl_xor_sync(0xffffffffu, v, 2);
            lacc[rbk][h] = v;
        }
    if (tig == 0) {
        SL[dcW * QM + rb + gid]      = lacc[0][0];
        SL[dcW * QM + rb + 8 + gid]  = lacc[0][1];
        SL[dcW * QM + rb + 16 + gid] = lacc[1][0];
        SL[dcW * QM + rb + 24 + gid] = lacc[1][1];
    }
    __syncthreads();

    float inv[2][2];
#pragma unroll
    for (int rbk = 0; rbk < 2; rbk++)
#pragma unroll
        for (int h = 0; h < 2; h++) {
            const int row = rb + rbk * 16 + h * 8 + gid;
            float s = SL[row] + SL[QM + row] + SL[2 * QM + row] + SL[3 * QM + row];
            inv[rbk][h] = 1.f / s;
        }

    // ---- epilogue ----
#pragma unroll
    for (int rbk = 0; rbk < 2; rbk++) {
        const int q = q0 + rb + rbk * 16 + gid;
#pragma unroll
        for (int n = 0; n < 8; n++) {
            const int d0 = dstart + n * 8 + 2 * tig;
            size_t i0 = ((size_t)(b * NC + d0)) * NPOS + q;
            out[i0]            = o[rbk][n][0] * inv[rbk][0] + x[i0];
            out[i0 + NPOS]     = o[rbk][n][1] * inv[rbk][0] + x[i0 + NPOS];
            out[i0 + 8]        = o[rbk][n][2] * inv[rbk][1] + x[i0 + 8];
            out[i0 + NPOS + 8] = o[rbk][n][3] * inv[rbk][1] + x[i0 + NPOS + 8];
        }
    }
}

// ---------------------------------------------------------------------------
extern "C" void kernel_launch(void* const* d_in, const int* in_sizes, int n_in,
                              void* d_out, int out_size)
{
    const float* x  = (const float*)d_in[0];
    const float* w1 = (const float*)d_in[1];
    const float* w2 = (const float*)d_in[2];
    const float* w3 = (const float*)d_in[3];
    float* out = (float*)d_out;

    cudaFuncSetAttribute(proj_kernel, cudaFuncAttributeMaxDynamicSharedMemorySize,
                         PROJ_SMEM);
    cudaFuncSetAttribute(attn_kernel, cudaFuncAttributeMaxDynamicSharedMemorySize,
                         SMEM_BYTES);

    dim3 gproj(NPOS / 256, 320 / 64, NB);   // (16, 5, 4)
    proj_kernel<<<gproj, 256, PROJ_SMEM>>>(x, w1, w2, w3);

    dim3 gqk(NPOS / QM, NB);                // (32, 4)
    qkmax_kernel<<<gqk, 512>>>();

    dim3 gattn(NPOS / QM, NB);              // (32, 4)
    attn_kernel<<<gattn, THREADS, SMEM_BYTES>>>(x, out);
}

// round 8
// speedup vs baseline: 9.6389x; 1.3566x over previous
#include <cuda_runtime.h>
#include <cuda_fp16.h>
#include <cstdint>

#define NB 4
#define NC 256
#define NK 32
#define NPOS 4096
#define QM 128
#define TK 128
#define NT (NPOS / TK)    // 32
#define THREADS 512
#define LOG2E 1.4426950408889634f

// ---------------- scratch (device globals; no allocs allowed) ---------------
__device__ __align__(128) __half g_X16[(size_t)NB * NC * NPOS]; // [b][c][n] fp16 copy of x
__device__ __align__(128) __half g_W16[320 * 256];              // Wcat fp16 (Q rows * log2e)
__device__ __align__(128) __half g_Q[(size_t)NB * NK * NPOS];   // [b][c][n]
__device__ __align__(128) __half g_K[(size_t)NB * NK * NPOS];   // [b][c][n]
__device__ __align__(128) __half g_V[(size_t)NB * NC * NPOS];   // [b][d][n]
__device__ __align__(128) float  g_M[(size_t)NB * NPOS];        // row maxes (log2 units)

// ---------------- helpers ---------------------------------------------------
__device__ __forceinline__ uint32_t s2u(const void* p) {
    uint32_t a;
    asm("{ .reg .u64 t; cvta.to.shared.u64 t, %1; cvt.u32.u64 %0, t; }"
        : "=r"(a) : "l"(p));
    return a;
}
__device__ __forceinline__ void cp16(uint32_t s, const void* g) {
    asm volatile("cp.async.cg.shared.global [%0], [%1], 16;" :: "r"(s), "l"(g));
}
#define CP_COMMIT() asm volatile("cp.async.commit_group;" ::: "memory")
#define CP_WAIT(n)  asm volatile("cp.async.wait_group %0;" :: "n"(n) : "memory")

__device__ __forceinline__ float ex2f(float x) {
    float r; asm("ex2.approx.f32 %0, %1;" : "=f"(r) : "f"(x)); return r;
}
__device__ __forceinline__ void mma16(float* c, const uint32_t* a,
                                      uint32_t b0, uint32_t b1) {
    asm volatile(
        "mma.sync.aligned.m16n8k16.row.col.f32.f16.f16.f32 "
        "{%0,%1,%2,%3}, {%4,%5,%6,%7}, {%8,%9}, {%0,%1,%2,%3};"
        : "+f"(c[0]), "+f"(c[1]), "+f"(c[2]), "+f"(c[3])
        : "r"(a[0]), "r"(a[1]), "r"(a[2]), "r"(a[3]), "r"(b0), "r"(b1));
}
__device__ __forceinline__ void ldsm4(uint32_t* r, uint32_t saddr) {
    asm volatile("ldmatrix.sync.aligned.m8n8.x4.shared.b16 {%0,%1,%2,%3}, [%4];"
        : "=r"(r[0]), "=r"(r[1]), "=r"(r[2]), "=r"(r[3]) : "r"(saddr));
}
__device__ __forceinline__ void ldsm4t(uint32_t* r, uint32_t saddr) {
    asm volatile("ldmatrix.sync.aligned.m8n8.x4.trans.shared.b16 {%0,%1,%2,%3}, [%4];"
        : "=r"(r[0]), "=r"(r[1]), "=r"(r[2]), "=r"(r[3]) : "r"(saddr));
}

// ---- attn smem (halfs / bytes) ----
#define QSTR 136
#define KSTR 136
#define VSH 136
#define PSH 136
#define SM_Q 0
#define QTILEB (32 * QSTR * 2)                 // 8704
#define SM_K (SM_Q + QTILEB)                   // 8704
#define KBUFB (32 * KSTR * 2)                  // 8704
#define SM_V (SM_K + 2 * KBUFB)                // 26112
#define VBUFB (NC * VSH * 2)                   // 69632
#define SM_P (SM_V + 2 * VBUFB)                // 165376
#define SM_L (SM_P + QM * PSH * 2)             // 200192
#define SMEM_BYTES (SM_L + 4 * QM * 4)         // 202240

// ---- proj smem ----
#define AST 264
#define BST 264
#define PROJ_A_B (64 * AST * 2)                // 33792
#define PROJ_BBUF (32 * BST * 2)               // 16896
#define PROJ_SMEM (PROJ_A_B + 2 * PROJ_BBUF)   // 67584

// ---------------------------------------------------------------------------
// cvt: x fp32 -> g_X16 (same [b][c][n] layout); w1/w2/w3 -> g_W16 (Q rows *log2e)
// ---------------------------------------------------------------------------
__global__ __launch_bounds__(256) void cvt_kernel(
    const float* __restrict__ x, const float* __restrict__ w1,
    const float* __restrict__ w2, const float* __restrict__ w3)
{
    const int bi = blockIdx.x, t = threadIdx.x;
    if (bi < NB * NC) {
        const float4* src = (const float4*)(x + (size_t)bi * NPOS);
        __half2* dst = (__half2*)(g_X16 + (size_t)bi * NPOS);
#pragma unroll
        for (int s = 0; s < 4; s++) {
            int i = t + s * 256;
            float4 v = src[i];
            dst[2 * i]     = __floats2half2_rn(v.x, v.y);
            dst[2 * i + 1] = __floats2half2_rn(v.z, v.w);
        }
    } else {
        const int base4 = (bi - NB * NC) * 1024;   // float4 index into 320*256
#pragma unroll
        for (int s = 0; s < 4; s++) {
            int i4 = base4 + t + s * 256;
            int e = i4 * 4;
            int k = e >> 8, c = e & 255;
            const float* wp = (k < 32) ? w1 + k * 256
                            : (k < 64) ? w2 + (k - 32) * 256
                                       : w3 + (k - 64) * 256;
            float4 v = *(const float4*)(wp + c);
            float sc = (k < 32) ? LOG2E : 1.f;
            __half2* dst = (__half2*)(g_W16 + (size_t)k * 256 + c);
            dst[0] = __floats2half2_rn(v.x * sc, v.y * sc);
            dst[1] = __floats2half2_rn(v.z * sc, v.w * sc);
        }
    }
}

// ---------------------------------------------------------------------------
// Projection as fp16 tensor-core GEMM. CTA: 64 k x 256 n, K=256.
// A = W16 [k][c] row-major (ldsm non-trans); B = X16 [c][n] (ldsm trans).
// 8 warps: mw = wid&3 (m16 block), nh = wid>>2 (128 n).
// ---------------------------------------------------------------------------
__global__ __launch_bounds__(256, 2) void proj_kernel()
{
    extern __shared__ __half PH[];
    const uint32_t sA = s2u(PH);
    const uint32_t sB = sA + PROJ_A_B;

    const int n0 = blockIdx.x * 256;
    const int k0 = blockIdx.y * 64;
    const int b  = blockIdx.z;
    const int t  = threadIdx.x;
    const int wid = t >> 5, lid = t & 31;
    const int mw = wid & 3, nh = wid >> 2;
    const int gid = lid >> 2, tig = lid & 3;

    // prologue: full A tile + B chunk 0
    {
#pragma unroll
        for (int s = 0; s < 8; s++) {
            int i = t + s * 256;
            int r = i >> 5, o = i & 31;
            cp16(sA + (r * AST + o * 8) * 2, g_W16 + (size_t)(k0 + r) * 256 + o * 8);
        }
#pragma unroll
        for (int s = 0; s < 4; s++) {
            int i = t + s * 256;
            int r = i >> 5, o = i & 31;
            cp16(sB + (r * BST + o * 8) * 2,
                 g_X16 + ((size_t)b * NC + r) * NPOS + n0 + o * 8);
        }
        CP_COMMIT();
    }

    float o[16][4];
#pragma unroll
    for (int n = 0; n < 16; n++)
#pragma unroll
        for (int c = 0; c < 4; c++) o[n][c] = 0.f;

    for (int ci = 0; ci < 8; ci++) {
        const int buf = ci & 1;
        CP_WAIT(0);
        __syncthreads();
        if (ci < 7) {
#pragma unroll
            for (int s = 0; s < 4; s++) {
                int i = t + s * 256;
                int r = i >> 5, o2 = i & 31;
                cp16(sB + ((buf ^ 1) * 32 * BST + r * BST + o2 * 8) * 2,
                     g_X16 + ((size_t)b * NC + (ci + 1) * 32 + r) * NPOS + n0 + o2 * 8);
            }
            CP_COMMIT();
        }
        const uint32_t bB = sB + buf * PROJ_BBUF;
#pragma unroll
        for (int kk2 = 0; kk2 < 2; kk2++) {
            uint32_t af[4];
            ldsm4(af, sA + ((mw * 16 + (lid & 15)) * AST +
                            ci * 32 + kk2 * 16 + ((lid >> 4) << 3)) * 2);
#pragma unroll
            for (int nb = 0; nb < 8; nb++) {
                uint32_t bf[4];
                ldsm4t(bf, bB + ((kk2 * 16 + (lid & 15)) * BST +
                                 nh * 128 + nb * 16 + ((lid >> 4) << 3)) * 2);
                mma16(o[2 * nb],     af, bf[0], bf[1]);
                mma16(o[2 * nb + 1], af, bf[2], bf[3]);
            }
        }
    }

    // epilogue: natural [k][n] half2 stores
#pragma unroll
    for (int hh = 0; hh < 2; hh++) {
        int k = k0 + mw * 16 + gid + hh * 8;
        __half* dst = (k < 32) ? g_Q + ((size_t)b * NK + k) * NPOS
                    : (k < 64) ? g_K + ((size_t)b * NK + (k - 32)) * NPOS
                               : g_V + ((size_t)b * NC + (k - 64)) * NPOS;
#pragma unroll
        for (int nb = 0; nb < 16; nb++) {
            int n = n0 + nh * 128 + nb * 8 + 2 * tig;
            *(__half2*)(dst + n) = __floats2half2_rn(o[nb][2 * hh], o[nb][2 * hh + 1]);
        }
    }
}

// ---------------------------------------------------------------------------
// Row-max pre-pass (Q,K c-major; trans-ldsm fragments).
// ---------------------------------------------------------------------------
__global__ __launch_bounds__(512) void qkmax_kernel()
{
    __shared__ __align__(16) __half Qs[32 * QSTR];
    __shared__ __align__(16) __half Ks[2 * 32 * KSTR];
    __shared__ float Mred[4 * QM];

    const uint32_t sbQ = s2u(Qs), sbK = s2u(Ks);
    const int t   = threadIdx.x;
    const int wid = t >> 5, lid = t & 31;
    const int mg  = wid & 3, dcW = wid >> 2;
    const int rb  = mg * 32, kbase = dcW * 32;
    const int b   = blockIdx.y;
    const int q0  = blockIdx.x * QM;

    const int qc = ((lid >> 4) << 3) | (lid & 7);   // A-trans c part
    const int qq = ((lid >> 3) & 1) << 3;           // A-trans q offset
    const int kc = lid & 15;                        // B-trans c part
    const int kn = (lid >> 4) << 3;                 // B-trans key offset

    const __half* Qg = g_Q + (size_t)b * NK * NPOS + q0;
    const __half* Kg = g_K + (size_t)b * NK * NPOS;

    {
        int c = t >> 4, o = t & 15;
        cp16(sbQ + (c * QSTR + o * 8) * 2, Qg + (size_t)c * NPOS + o * 8);
        cp16(sbK + (c * KSTR + o * 8) * 2, Kg + (size_t)c * NPOS + o * 8);
        CP_COMMIT();
    }

    float mx0[2] = {-1e30f, -1e30f}, mx1[2] = {-1e30f, -1e30f};
    uint32_t qf[2][2][4];
    bool qloaded = false;

    for (int j = 0; j < NT; j++) {
        const int cur = j & 1;
        CP_WAIT(0);
        __syncthreads();
        if (!qloaded) {
            qloaded = true;
#pragma unroll
            for (int rbk = 0; rbk < 2; rbk++)
#pragma unroll
                for (int kk = 0; kk < 2; kk++)
                    ldsm4t(qf[rbk][kk],
                           sbQ + ((kk * 16 + qc) * QSTR + rb + rbk * 16 + qq) * 2);
        }
        if (j + 1 < NT) {
            int c = t >> 4, o = t & 15;
            cp16(sbK + ((1 - cur) * 32 * KSTR + c * KSTR + o * 8) * 2,
                 Kg + (size_t)c * NPOS + (size_t)(j + 1) * TK + o * 8);
            CP_COMMIT();
        }
        const uint32_t kbB = sbK + cur * 32 * (KSTR * 2);
#pragma unroll
        for (int nbp = 0; nbp < 2; nbp++) {
            uint32_t kf[2][4];
#pragma unroll
            for (int kk = 0; kk < 2; kk++)
                ldsm4t(kf[kk],
                       kbB + ((kk * 16 + kc) * KSTR + kbase + nbp * 16 + kn) * 2);
#pragma unroll
            for (int rbk = 0; rbk < 2; rbk++) {
                float s4[2][4] = {{0.f,0.f,0.f,0.f},{0.f,0.f,0.f,0.f}};
#pragma unroll
                for (int kk = 0; kk < 2; kk++) {
                    mma16(s4[0], qf[rbk][kk], kf[kk][0], kf[kk][1]);
                    mma16(s4[1], qf[rbk][kk], kf[kk][2], kf[kk][3]);
                }
#pragma unroll
                for (int nb2 = 0; nb2 < 2; nb2++) {
                    mx0[rbk] = fmaxf(mx0[rbk], fmaxf(s4[nb2][0], s4[nb2][1]));
                    mx1[rbk] = fmaxf(mx1[rbk], fmaxf(s4[nb2][2], s4[nb2][3]));
                }
            }
        }
    }

    const int gid = lid >> 2, tig = lid & 3;
#pragma unroll
    for (int rbk = 0; rbk < 2; rbk++) {
        mx0[rbk] = fmaxf(mx0[rbk], __shfl_xor_sync(0xffffffffu, mx0[rbk], 1));
        mx0[rbk] = fmaxf(mx0[rbk], __shfl_xor_sync(0xffffffffu, mx0[rbk], 2));
        mx1[rbk] = fmaxf(mx1[rbk], __shfl_xor_sync(0xffffffffu, mx1[rbk], 1));
        mx1[rbk] = fmaxf(mx1[rbk], __shfl_xor_sync(0xffffffffu, mx1[rbk], 2));
    }
    if (tig == 0) {
        Mred[dcW * QM + rb + gid]      = mx0[0];
        Mred[dcW * QM + rb + 8 + gid]  = mx1[0];
        Mred[dcW * QM + rb + 16 + gid] = mx0[1];
        Mred[dcW * QM + rb + 24 + gid] = mx1[1];
    }
    __syncthreads();
    if (t < QM) {
        float m = fmaxf(fmaxf(Mred[t], Mred[QM + t]),
                        fmaxf(Mred[2 * QM + t], Mred[3 * QM + t]));
        g_M[(size_t)b * NPOS + q0 + t] = m;
    }
}

// ---------------------------------------------------------------------------
// fp16 flash attention (Q,K c-major; trans-ldsm for QK fragments).
// ---------------------------------------------------------------------------
__global__ __launch_bounds__(THREADS) void attn_kernel(
    const float* __restrict__ x, float* __restrict__ out)
{
    extern __shared__ __align__(16) char sm[];
    const uint32_t sb = s2u(sm);
    __half* Ps = (__half*)(sm + SM_P);
    float* SL  = (float*)(sm + SM_L);

    const int t   = threadIdx.x;
    const int wid = t >> 5, lid = t & 31;
    const int gid = lid >> 2, tig = lid & 3;
    const int mg  = wid & 3, dcW = wid >> 2;
    const int rb  = mg * 32;
    const int kbase  = dcW * 32;
    const int dstart = dcW * 64;
    const int b  = blockIdx.y;
    const int q0 = blockIdx.x * QM;

    const int qc = ((lid >> 4) << 3) | (lid & 7);
    const int qq = ((lid >> 3) & 1) << 3;
    const int kc = lid & 15;
    const int kn = (lid >> 4) << 3;
    const int arow  = lid & 15;            // for non-trans (P, V frags)
    const int acolh = (lid >> 4) << 3;
    const int brow  = ((lid >> 4) << 3) | (lid & 7);
    const int bcolh = ((lid >> 3) & 1) << 3;

    const __half* Qg = g_Q + (size_t)b * NK * NPOS + q0;
    const __half* Kg = g_K + (size_t)b * NK * NPOS;
    const __half* Vg = g_V + (size_t)b * NC * NPOS;

    const float* Mg = g_M + (size_t)b * NPOS + q0;
    float m0[2], m1[2];
    m0[0] = Mg[rb + gid];      m1[0] = Mg[rb + 8 + gid];
    m0[1] = Mg[rb + 16 + gid]; m1[1] = Mg[rb + 24 + gid];

    {
        int c = t >> 4, o = t & 15;
        cp16(sb + SM_Q + (c * QSTR + o * 8) * 2, Qg + (size_t)c * NPOS + o * 8);
        cp16(sb + SM_K + (c * KSTR + o * 8) * 2, Kg + (size_t)c * NPOS + o * 8);
#pragma unroll
        for (int s = 0; s < 8; s++) {
            int i = t + s * THREADS;
            int d = i >> 4, k4 = i & 15;
            cp16(sb + SM_V + d * (VSH * 2) + k4 * 16, Vg + (size_t)d * NPOS + k4 * 8);
        }
        CP_COMMIT();
    }

    float o[2][8][4];
#pragma unroll
    for (int r = 0; r < 2; r++)
#pragma unroll
        for (int n = 0; n < 8; n++)
#pragma unroll
            for (int c = 0; c < 4; c++) o[r][n][c] = 0.f;

    float lacc[2][2] = {{0.f, 0.f}, {0.f, 0.f}};
    uint32_t qf[2][2][4];
    bool qloaded = false;

    for (int j = 0; j < NT; j++) {
        const int cur = j & 1;
        CP_WAIT(0);
        __syncthreads();

        if (!qloaded) {
            qloaded = true;
#pragma unroll
            for (int rbk = 0; rbk < 2; rbk++)
#pragma unroll
                for (int kk = 0; kk < 2; kk++)
                    ldsm4t(qf[rbk][kk],
                           sb + SM_Q + ((kk * 16 + qc) * QSTR + rb + rbk * 16 + qq) * 2);
        }

        if (j + 1 < NT) {
            const size_t koff = (size_t)(j + 1) * TK;
            int c = t >> 4, o2 = t & 15;
            cp16(sb + SM_K + ((1 - cur) * 32 * KSTR + c * KSTR + o2 * 8) * 2,
                 Kg + (size_t)c * NPOS + koff + o2 * 8);
#pragma unroll
            for (int s = 0; s < 8; s++) {
                int i = t + s * THREADS;
                int d = i >> 4, k4 = i & 15;
                cp16(sb + SM_V + (1 - cur) * VBUFB + d * (VSH * 2) + k4 * 16,
                     Vg + (size_t)d * NPOS + koff + k4 * 8);
            }
            CP_COMMIT();
        }

        // ---- phase A: S = Q K^T, e = 2^(s-m), P -> smem ----
        {
            const uint32_t kbB = sb + SM_K + cur * KBUFB;
#pragma unroll
            for (int nbp = 0; nbp < 2; nbp++) {
                uint32_t kf[2][4];
#pragma unroll
                for (int kk = 0; kk < 2; kk++)
                    ldsm4t(kf[kk],
                           kbB + ((kk * 16 + kc) * KSTR + kbase + nbp * 16 + kn) * 2);
#pragma unroll
                for (int rbk = 0; rbk < 2; rbk++) {
                    float s4[2][4] = {{0.f,0.f,0.f,0.f},{0.f,0.f,0.f,0.f}};
#pragma unroll
                    for (int kk = 0; kk < 2; kk++) {
                        mma16(s4[0], qf[rbk][kk], kf[kk][0], kf[kk][1]);
                        mma16(s4[1], qf[rbk][kk], kf[kk][2], kf[kk][3]);
                    }
                    const int q = rb + rbk * 16 + gid;
#pragma unroll
                    for (int nb2 = 0; nb2 < 2; nb2++) {
                        float e0 = ex2f(s4[nb2][0] - m0[rbk]);
                        float e1 = ex2f(s4[nb2][1] - m0[rbk]);
                        float e2 = ex2f(s4[nb2][2] - m1[rbk]);
                        float e3 = ex2f(s4[nb2][3] - m1[rbk]);
                        lacc[rbk][0] += e0 + e1;
                        lacc[rbk][1] += e2 + e3;
                        const int col = kbase + nbp * 16 + nb2 * 8 + 2 * tig;
                        *(__half2*)&Ps[q * PSH + col]       = __floats2half2_rn(e0, e1);
                        *(__half2*)&Ps[(q + 8) * PSH + col] = __floats2half2_rn(e2, e3);
                    }
                }
            }
        }
        __syncthreads();

        // ---- phase B: O += P @ V (P,V non-trans frags, unchanged) ----
        {
            const uint32_t vbB = sb + SM_V + cur * VBUFB;
#pragma unroll
            for (int kk = 0; kk < 8; kk++) {
                uint32_t pf[2][4];
#pragma unroll
                for (int rbk = 0; rbk < 2; rbk++)
                    ldsm4(pf[rbk],
                          sb + SM_P + ((rb + rbk * 16 + arow) * PSH + kk * 16 + acolh) * 2);
#pragma unroll
                for (int dp = 0; dp < 4; dp++) {
                    uint32_t vf[4];
                    ldsm4(vf, vbB + ((dstart + dp * 16 + brow) * VSH + kk * 16 + bcolh) * 2);
                    mma16(o[0][2 * dp],     pf[0], vf[0], vf[1]);
                    mma16(o[0][2 * dp + 1], pf[0], vf[2], vf[3]);
                    mma16(o[1][2 * dp],     pf[1], vf[0], vf[1]);
                    mma16(o[1][2 * dp + 1], pf[1], vf[2], vf[3]);
                }
            }
        }
    }

    // ---- denominators ----
#pragma unroll
    for (int rbk = 0; rbk < 2; rbk++)
#pragma unroll
        for (int h = 0; h < 2; h++) {
            float v = lacc[rbk][h];
            v += __shfl_xor_sync(0xffffffffu, v, 1);
            v += __shfl_xor_sync(0xffffffffu, v, 2);
            lacc[rbk][h] = v;
        }
    if (tig == 0) {
        SL[dcW * QM + rb + gid]      = lacc[0][0];
        SL[dcW * QM + rb + 8 + gid]  = lacc[0][1];
        SL[dcW * QM + rb + 16 + gid] = lacc[1][0];
        SL[dcW * QM + rb + 24 + gid] = lacc[1][1];
    }
    __syncthreads();

    float inv[2][2];
#pragma unroll
    for (int rbk = 0; rbk < 2; rbk++)
#pragma unroll
        for (int h = 0; h < 2; h++) {
            const int row = rb + rbk * 16 + h * 8 + gid;
            float s = SL[row] + SL[QM + row] + SL[2 * QM + row] + SL[3 * QM + row];
            inv[rbk][h] = 1.f / s;
        }

    // ---- epilogue ----
#pragma unroll
    for (int rbk = 0; rbk < 2; rbk++) {
        const int q = q0 + rb + rbk * 16 + gid;
#pragma unroll
        for (int n = 0; n < 8; n++) {
            const int d0 = dstart + n * 8 + 2 * tig;
            size_t i0 = ((size_t)(b * NC + d0)) * NPOS + q;
            out[i0]            = o[rbk][n][0] * inv[rbk][0] + x[i0];
            out[i0 + NPOS]     = o[rbk][n][1] * inv[rbk][0] + x[i0 + NPOS];
            out[i0 + 8]        = o[rbk][n][2] * inv[rbk][1] + x[i0 + 8];
            out[i0 + NPOS + 8] = o[rbk][n][3] * inv[rbk][1] + x[i0 + NPOS + 8];
        }
    }
}

// ---------------------------------------------------------------------------
extern "C" void kernel_launch(void* const* d_in, const int* in_sizes, int n_in,
                              void* d_out, int out_size)
{
    const float* x  = (const float*)d_in[0];
    const float* w1 = (const float*)d_in[1];
    const float* w2 = (const float*)d_in[2];
    const float* w3 = (const float*)d_in[3];
    float* out = (float*)d_out;

    cudaFuncSetAttribute(proj_kernel, cudaFuncAttributeMaxDynamicSharedMemorySize,
                         PROJ_SMEM);
    cudaFuncSetAttribute(attn_kernel, cudaFuncAttributeMaxDynamicSharedMemorySize,
                         SMEM_BYTES);

    cvt_kernel<<<NB * NC + 20, 256>>>(x, w1, w2, w3);

    dim3 gproj(NPOS / 256, 320 / 64, NB);   // (16, 5, 4)
    proj_kernel<<<gproj, 256, PROJ_SMEM>>>();

    dim3 gqk(NPOS / QM, NB);                // (32, 4)
    qkmax_kernel<<<gqk, 512>>>();

    dim3 gattn(NPOS / QM, NB);              // (32, 4)
    attn_kernel<<<gattn, THREADS, SMEM_BYTES>>>(x, out);
}